// round 5
// baseline (speedup 1.0000x reference)
#include <cuda_runtime.h>
#include <math.h>
#include <float.h>

#define NN 50000
#define EE 800000

// ---------------- persistent scratch (device globals; no allocation) ----------------
__device__ float g_ft [NN * 160];   // per-layer transformed features [N, H*F]
__device__ float g_rst[NN * 160];   // accumulator: skip + bias + messages
__device__ float g_h  [NN * 128];   // activations between layers
__device__ float g_el [NN * 4];
__device__ float g_er [NN * 4];
__device__ float g_m  [NN * 4];     // segment max
__device__ float g_s  [NN * 4];     // segment sum of exp
__device__ float g_ex [EE * 4];     // exp(e - m[dst]) per edge/head
__device__ float g_bnsum[128];
__device__ float g_bnsq [128];

__device__ __forceinline__ float lrelu(float x) { return x > 0.f ? x : 0.2f * x; }

__device__ __forceinline__ void atomicMaxF(float* addr, float v) {
    if (v >= 0.f) atomicMax((int*)addr, __float_as_int(v));
    else          atomicMin((unsigned int*)addr, (unsigned int)__float_as_int(v));
}

// ---------------- GEMM: out[n, c] = sum_k X[n,k] * W[k,c] (+ bias) ----------------
// K = 128 fixed. Block: 64 rows x 32 cols, 128 threads, each thread 4x4, K-chunks of 64.
template<int OD>
__global__ __launch_bounds__(128)
void gemm_k128(const float* __restrict__ X, const float* __restrict__ W,
               const float* __restrict__ bias, float* __restrict__ out)
{
    __shared__ float Xs[64 * 65];   // [row][k] padded
    __shared__ float Ws[64 * 32];   // [k][col]
    const int tid  = threadIdx.x;
    const int tx   = tid & 7;       // col group (x4)
    const int ty   = tid >> 3;      // row group (x4), 0..15
    const int row0 = blockIdx.x * 64;
    const int col0 = blockIdx.y * 32;

    float acc[4][4];
#pragma unroll
    for (int i = 0; i < 4; i++)
#pragma unroll
        for (int j = 0; j < 4; j++) acc[i][j] = 0.f;

#pragma unroll
    for (int kb = 0; kb < 128; kb += 64) {
        // load X tile (64 rows x 64 k), vectorized, coalesced
#pragma unroll
        for (int j = 0; j < 8; j++) {
            int i4 = tid + j * 128;          // 0..1023 float4 slots
            int r  = i4 >> 4;
            int k4 = (i4 & 15) << 2;
            float4 v = make_float4(0.f, 0.f, 0.f, 0.f);
            if (row0 + r < NN)
                v = *(const float4*)(X + (size_t)(row0 + r) * 128 + kb + k4);
            float* xp = &Xs[r * 65 + k4];
            xp[0] = v.x; xp[1] = v.y; xp[2] = v.z; xp[3] = v.w;
        }
        // load W tile (64 k x 32 cols)
#pragma unroll
        for (int j = 0; j < 4; j++) {
            int i4 = tid + j * 128;          // 0..511 float4 slots
            int k  = i4 >> 3;
            int c4 = (i4 & 7) << 2;
            *(float4*)&Ws[k * 32 + c4] =
                *(const float4*)(W + (size_t)(kb + k) * OD + col0 + c4);
        }
        __syncthreads();
#pragma unroll 8
        for (int k = 0; k < 64; k++) {
            float4 w = *(const float4*)&Ws[k * 32 + tx * 4];
            float x0 = Xs[(ty * 4 + 0) * 65 + k];
            float x1 = Xs[(ty * 4 + 1) * 65 + k];
            float x2 = Xs[(ty * 4 + 2) * 65 + k];
            float x3 = Xs[(ty * 4 + 3) * 65 + k];
            acc[0][0] += x0 * w.x; acc[0][1] += x0 * w.y; acc[0][2] += x0 * w.z; acc[0][3] += x0 * w.w;
            acc[1][0] += x1 * w.x; acc[1][1] += x1 * w.y; acc[1][2] += x1 * w.z; acc[1][3] += x1 * w.w;
            acc[2][0] += x2 * w.x; acc[2][1] += x2 * w.y; acc[2][2] += x2 * w.z; acc[2][3] += x2 * w.w;
            acc[3][0] += x3 * w.x; acc[3][1] += x3 * w.y; acc[3][2] += x3 * w.z; acc[3][3] += x3 * w.w;
        }
        __syncthreads();
    }

    float4 bb = make_float4(0.f, 0.f, 0.f, 0.f);
    if (bias) bb = *(const float4*)(bias + col0 + tx * 4);
#pragma unroll
    for (int i = 0; i < 4; i++) {
        int r = row0 + ty * 4 + i;
        if (r < NN) {
            float4 o;
            o.x = acc[i][0] + bb.x;
            o.y = acc[i][1] + bb.y;
            o.z = acc[i][2] + bb.z;
            o.w = acc[i][3] + bb.w;
            *(float4*)(out + (size_t)r * OD + col0 + tx * 4) = o;
        }
    }
}

// ---------------- el/er = <ft[n,h,:], al/ar[h,:]>; also init m, s ----------------
template<int F>
__global__ void elr_kernel(const float* __restrict__ al, const float* __restrict__ ar)
{
    int i = blockIdx.x * blockDim.x + threadIdx.x;   // over N*H
    if (i >= NN * 4) return;
    int h = i & 3;
    const float* f = g_ft + (size_t)(i >> 2) * (4 * F) + h * F;
    float a = 0.f, b = 0.f;
#pragma unroll
    for (int j = 0; j < F; j++) {
        float v = f[j];
        a += v * __ldg(al + h * F + j);
        b += v * __ldg(ar + h * F + j);
    }
    g_el[i] = a;
    g_er[i] = b;
    g_m[i]  = -FLT_MAX;
    g_s[i]  = 0.f;
}

// ---------------- edge pass A: segment max ----------------
__global__ void edge_max_kernel(const int* __restrict__ src, const int* __restrict__ dst)
{
    int e = blockIdx.x * blockDim.x + threadIdx.x;
    if (e >= EE) return;
    int sn = src[e], dn = dst[e];
    float4 l = *(const float4*)(g_el + (size_t)sn * 4);
    float4 r = *(const float4*)(g_er + (size_t)dn * 4);
    float* mp = g_m + (size_t)dn * 4;
    atomicMaxF(mp + 0, lrelu(l.x + r.x));
    atomicMaxF(mp + 1, lrelu(l.y + r.y));
    atomicMaxF(mp + 2, lrelu(l.z + r.z));
    atomicMaxF(mp + 3, lrelu(l.w + r.w));
}

// ---------------- edge pass B: ex = exp(e - m[dst]); s += ex ----------------
__global__ void edge_sum_kernel(const int* __restrict__ src, const int* __restrict__ dst)
{
    int e = blockIdx.x * blockDim.x + threadIdx.x;
    if (e >= EE) return;
    int sn = src[e], dn = dst[e];
    float4 l = *(const float4*)(g_el + (size_t)sn * 4);
    float4 r = *(const float4*)(g_er + (size_t)dn * 4);
    float4 m = *(const float4*)(g_m  + (size_t)dn * 4);
    float4 ex;
    ex.x = expf(lrelu(l.x + r.x) - m.x);
    ex.y = expf(lrelu(l.y + r.y) - m.y);
    ex.z = expf(lrelu(l.z + r.z) - m.z);
    ex.w = expf(lrelu(l.w + r.w) - m.w);
    *(float4*)(g_ex + (size_t)e * 4) = ex;
    float* sp = g_s + (size_t)dn * 4;
    atomicAdd(sp + 0, ex.x);
    atomicAdd(sp + 1, ex.y);
    atomicAdd(sp + 2, ex.z);
    atomicAdd(sp + 3, ex.w);
}

// ---------------- edge pass C: rst[dst] += a * ft[src] (warp per edge) ----------------
template<int OD, int F>
__global__ void edge_aggr_kernel(const int* __restrict__ src, const int* __restrict__ dst)
{
    int w = (blockIdx.x * blockDim.x + threadIdx.x) >> 5;
    if (w >= EE) return;
    int lane = threadIdx.x & 31;
    int sn = __ldg(src + w), dn = __ldg(dst + w);
    float4 ex = *(const float4*)(g_ex + (size_t)w * 4);
    float4 sv = *(const float4*)(g_s  + (size_t)dn * 4);
    float a[4] = { ex.x / sv.x, ex.y / sv.y, ex.z / sv.z, ex.w / sv.w };
    const float4* fp = (const float4*)(g_ft + (size_t)sn * OD);
    float* rp = g_rst + (size_t)dn * OD;
#pragma unroll
    for (int j4 = lane; j4 < OD / 4; j4 += 32) {
        float4 f = fp[j4];
        float av = a[(j4 * 4) / F];
        asm volatile("red.global.add.v4.f32 [%0], {%1,%2,%3,%4};"
                     :: "l"(rp + j4 * 4),
                        "f"(f.x * av), "f"(f.y * av), "f"(f.z * av), "f"(f.w * av)
                     : "memory");
    }
}

// ---------------- batchnorm ----------------
__global__ void bn_init_kernel()
{
    int t = threadIdx.x;
    if (t < 128) { g_bnsum[t] = 0.f; g_bnsq[t] = 0.f; }
}

__global__ void bn_stats_kernel(const float* __restrict__ x)
{
    __shared__ float ss[256], sq[256];
    int c    = threadIdx.x & 127;
    int half = threadIdx.x >> 7;
    int r0   = blockIdx.x * 256 + half;
    int rend = min(NN, (int)(blockIdx.x + 1) * 256);
    float s = 0.f, q = 0.f;
    for (int r = r0; r < rend; r += 2) {
        float v = x[(size_t)r * 128 + c];
        s += v; q += v * v;
    }
    ss[threadIdx.x] = s; sq[threadIdx.x] = q;
    __syncthreads();
    if (threadIdx.x < 128) {
        atomicAdd(&g_bnsum[c], ss[c] + ss[c + 128]);
        atomicAdd(&g_bnsq[c],  sq[c] + sq[c + 128]);
    }
}

__global__ void bn_apply_kernel(const float* __restrict__ x, const float* __restrict__ gam,
                                const float* __restrict__ be, float* __restrict__ out)
{
    int i = blockIdx.x * blockDim.x + threadIdx.x;
    if (i >= NN * 128) return;
    int c = i & 127;
    const float invN = 1.f / (float)NN;
    float mean = g_bnsum[c] * invN;
    float var  = g_bnsq[c] * invN - mean * mean;
    float v = (x[i] - mean) * rsqrtf(var + 1e-5f) * __ldg(gam + c) + __ldg(be + c);
    out[i] = fmaxf(v, 0.f);
}

// ---------------- final: mean over heads + bias, log_softmax (warp per node) ----------------
__global__ void final_kernel(const float* __restrict__ bias_last, float* __restrict__ out)
{
    int gw = (blockIdx.x * blockDim.x + threadIdx.x) >> 5;
    if (gw >= NN) return;
    int lane = threadIdx.x & 31;
    const float* r = g_rst + (size_t)gw * 160;

    float v0 = 0.25f * (r[lane] + r[40 + lane] + r[80 + lane] + r[120 + lane])
             + __ldg(bias_last + lane);
    float v1 = -FLT_MAX;
    if (lane < 8) {
        int c1 = lane + 32;
        v1 = 0.25f * (r[c1] + r[40 + c1] + r[80 + c1] + r[120 + c1])
           + __ldg(bias_last + c1);
    }
    float mx = fmaxf(v0, v1);
#pragma unroll
    for (int o = 16; o; o >>= 1) mx = fmaxf(mx, __shfl_xor_sync(0xffffffffu, mx, o));
    float se = expf(v0 - mx) + (lane < 8 ? expf(v1 - mx) : 0.f);
#pragma unroll
    for (int o = 16; o; o >>= 1) se += __shfl_xor_sync(0xffffffffu, se, o);
    float lse = logf(se);
    out[(size_t)gw * 40 + lane] = v0 - mx - lse;
    if (lane < 8) out[(size_t)gw * 40 + lane + 32] = v1 - mx - lse;
}

// ---------------- launch ----------------
extern "C" void kernel_launch(void* const* d_in, const int* in_sizes, int n_in,
                              void* d_out, int out_size)
{
    (void)in_sizes; (void)n_in; (void)out_size;
    const float* feat   = (const float*)d_in[0];
    const int*   src    = (const int*)  d_in[1];
    const int*   dst    = (const int*)  d_in[2];
    const float* w_fc0  = (const float*)d_in[3];
    const float* al0    = (const float*)d_in[4];
    const float* ar0    = (const float*)d_in[5];
    const float* b0     = (const float*)d_in[6];
    const float* w_lin0 = (const float*)d_in[7];
    const float* gam0   = (const float*)d_in[8];
    const float* be0    = (const float*)d_in[9];
    const float* w_fc1  = (const float*)d_in[10];
    const float* al1    = (const float*)d_in[11];
    const float* ar1    = (const float*)d_in[12];
    const float* b1     = (const float*)d_in[13];
    const float* w_lin1 = (const float*)d_in[14];
    const float* gam1   = (const float*)d_in[15];
    const float* be1    = (const float*)d_in[16];
    const float* w_fc2  = (const float*)d_in[17];
    const float* al2    = (const float*)d_in[18];
    const float* ar2    = (const float*)d_in[19];
    const float* b2     = (const float*)d_in[20];
    const float* w_lin2 = (const float*)d_in[21];
    const float* blast  = (const float*)d_in[22];

    float *ft, *rst, *h;
    cudaGetSymbolAddress((void**)&ft,  g_ft);
    cudaGetSymbolAddress((void**)&rst, g_rst);
    cudaGetSymbolAddress((void**)&h,   g_h);

    const dim3 g128((NN + 63) / 64, 4);
    const dim3 g160((NN + 63) / 64, 5);
    const int EB   = (EE + 255) / 256;
    const int AGGB = (int)(((long long)EE * 32 + 255) / 256);
    const int NHB  = (NN * 4 + 255) / 256;
    const int NEL  = (NN * 128 + 255) / 256;
    const int BNB  = (NN + 255) / 256;
    const int FNB  = (NN * 32 + 255) / 256;

    // ---- layer 0 (in=128, OD=128, F=32) ----
    gemm_k128<128><<<g128, 128>>>(feat, w_fc0, nullptr, ft);
    gemm_k128<128><<<g128, 128>>>(feat, w_lin0, b0, rst);
    elr_kernel<32><<<NHB, 256>>>(al0, ar0);
    edge_max_kernel<<<EB, 256>>>(src, dst);
    edge_sum_kernel<<<EB, 256>>>(src, dst);
    edge_aggr_kernel<128, 32><<<AGGB, 256>>>(src, dst);
    bn_init_kernel<<<1, 128>>>();
    bn_stats_kernel<<<BNB, 256>>>(rst);
    bn_apply_kernel<<<NEL, 256>>>(rst, gam0, be0, h);

    // ---- layer 1 (in=128, OD=128, F=32) ----
    gemm_k128<128><<<g128, 128>>>(h, w_fc1, nullptr, ft);
    gemm_k128<128><<<g128, 128>>>(h, w_lin1, b1, rst);
    elr_kernel<32><<<NHB, 256>>>(al1, ar1);
    edge_max_kernel<<<EB, 256>>>(src, dst);
    edge_sum_kernel<<<EB, 256>>>(src, dst);
    edge_aggr_kernel<128, 32><<<AGGB, 256>>>(src, dst);
    bn_init_kernel<<<1, 128>>>();
    bn_stats_kernel<<<BNB, 256>>>(rst);
    bn_apply_kernel<<<NEL, 256>>>(rst, gam1, be1, h);

    // ---- layer 2 (in=128, OD=160, F=40) ----
    gemm_k128<160><<<g160, 128>>>(h, w_fc2, nullptr, ft);
    gemm_k128<160><<<g160, 128>>>(h, w_lin2, b2, rst);
    elr_kernel<40><<<NHB, 256>>>(al2, ar2);
    edge_max_kernel<<<EB, 256>>>(src, dst);
    edge_sum_kernel<<<EB, 256>>>(src, dst);
    edge_aggr_kernel<160, 40><<<AGGB, 256>>>(src, dst);
    final_kernel<<<FNB, 256>>>(blast, (float*)d_out);
}

// round 6
// speedup vs baseline: 1.1562x; 1.1562x over previous
#include <cuda_runtime.h>
#include <math.h>
#include <float.h>

#define NN 50000
#define EE 800000

// ---------------- persistent scratch (device globals; no allocation) ----------------
__device__ float g_ft [NN * 160];   // per-layer transformed features [N, H*F]
__device__ float g_rst[NN * 160];   // accumulator: skip + bias + messages
__device__ float g_h  [NN * 128];   // activations between layers
__device__ float g_el [NN * 4];
__device__ float g_er [NN * 4];
__device__ float g_m  [NN * 4];     // segment max
__device__ float g_s  [NN * 4];     // segment sum of exp
__device__ float g_ex [EE * 4];     // per-edge logits, then exp(e - m[dst])
__device__ float g_bnsum[128];
__device__ float g_bnsq [128];

__device__ __forceinline__ float lrelu(float x) { return x > 0.f ? x : 0.2f * x; }

__device__ __forceinline__ void atomicMaxF(float* addr, float v) {
    if (v >= 0.f) atomicMax((int*)addr, __float_as_int(v));
    else          atomicMin((unsigned int*)addr, (unsigned int)__float_as_int(v));
}

__device__ __forceinline__ float tf32r(float x) {
    unsigned u;
    asm("cvt.rna.tf32.f32 %0, %1;" : "=r"(u) : "f"(x));
    return __uint_as_float(u);
}

__device__ __forceinline__ void mma_tf32(float* c, const unsigned* a, const unsigned* b) {
    asm volatile(
        "mma.sync.aligned.m16n8k8.row.col.f32.tf32.tf32.f32 "
        "{%0,%1,%2,%3}, {%4,%5,%6,%7}, {%8,%9}, {%0,%1,%2,%3};\n"
        : "+f"(c[0]), "+f"(c[1]), "+f"(c[2]), "+f"(c[3])
        : "r"(a[0]), "r"(a[1]), "r"(a[2]), "r"(a[3]), "r"(b[0]), "r"(b[1]));
}

// ---------------- tf32 tensor-core GEMM: out[n,c] = sum_k X[n,k] W[k,c] (+bias) ----
// K = 128. Block tile 128x32, 4 warps (each 32x32 = 2x4 mma m16n8k8), BK = 32.
// Smem pads of 37 make every fragment load and smem store bank-conflict-free.
template<int OD>
__global__ __launch_bounds__(128)
void gemm_tc(const float* __restrict__ X, const float* __restrict__ W,
             const float* __restrict__ bias, float* __restrict__ out)
{
    __shared__ float As[128 * 37];   // [m][k]
    __shared__ float Bs[32 * 37];    // [n][k]  (transposed on load)
    const int tid  = threadIdx.x;
    const int warp = tid >> 5, lane = tid & 31;
    const int g    = lane >> 2, t = lane & 3;
    const int row0 = blockIdx.x * 128;
    const int col0 = blockIdx.y * 32;

    float c[2][4][4];
#pragma unroll
    for (int i = 0; i < 2; i++)
#pragma unroll
        for (int j = 0; j < 4; j++)
#pragma unroll
            for (int q = 0; q < 4; q++) c[i][j][q] = 0.f;

#pragma unroll
    for (int kb = 0; kb < 128; kb += 32) {
        // A tile: 128 rows x 32 k, float4 coalesced, tf32-rounded into smem
#pragma unroll
        for (int j = 0; j < 8; j++) {
            int i4 = tid + j * 128;          // 0..1023 float4 slots (8 per row)
            int r  = i4 >> 3;
            int k4 = (i4 & 7) << 2;
            float4 v = make_float4(0.f, 0.f, 0.f, 0.f);
            if (row0 + r < NN)
                v = *(const float4*)(X + (size_t)(row0 + r) * 128 + kb + k4);
            float* ap = &As[r * 37 + k4];
            ap[0] = tf32r(v.x); ap[1] = tf32r(v.y); ap[2] = tf32r(v.z); ap[3] = tf32r(v.w);
        }
        // B tile: 32 k x 32 n, transpose into Bs[n][k]
#pragma unroll
        for (int j = 0; j < 2; j++) {
            int i4 = tid + j * 128;          // 0..255 float4 slots
            int k  = i4 >> 3;
            int n4 = (i4 & 7) << 2;
            float4 v = *(const float4*)(W + (size_t)(kb + k) * OD + col0 + n4);
            Bs[(n4 + 0) * 37 + k] = tf32r(v.x);
            Bs[(n4 + 1) * 37 + k] = tf32r(v.y);
            Bs[(n4 + 2) * 37 + k] = tf32r(v.z);
            Bs[(n4 + 3) * 37 + k] = tf32r(v.w);
        }
        __syncthreads();
#pragma unroll
        for (int ks = 0; ks < 4; ks++) {
            const int k0 = ks * 8;
            unsigned a[2][4], b[4][2];
            const int mbase = warp * 32;
#pragma unroll
            for (int i = 0; i < 2; i++) {
                const float* ap = As + (mbase + i * 16 + g) * 37 + k0 + t;
                a[i][0] = __float_as_uint(ap[0]);
                a[i][1] = __float_as_uint(ap[8 * 37]);
                a[i][2] = __float_as_uint(ap[4]);
                a[i][3] = __float_as_uint(ap[8 * 37 + 4]);
            }
#pragma unroll
            for (int j = 0; j < 4; j++) {
                const float* bp = Bs + (j * 8 + g) * 37 + k0 + t;
                b[j][0] = __float_as_uint(bp[0]);
                b[j][1] = __float_as_uint(bp[4]);
            }
#pragma unroll
            for (int i = 0; i < 2; i++)
#pragma unroll
                for (int j = 0; j < 4; j++)
                    mma_tf32(c[i][j], a[i], b[j]);
        }
        __syncthreads();
    }

    // epilogue: c0,c1 -> (row g, col 2t..2t+1); c2,c3 -> (row g+8)
#pragma unroll
    for (int i = 0; i < 2; i++) {
        int r = row0 + warp * 32 + i * 16 + g;
#pragma unroll
        for (int j = 0; j < 4; j++) {
            int cc = col0 + j * 8 + 2 * t;
            float bx = 0.f, by = 0.f;
            if (bias) { bx = __ldg(bias + cc); by = __ldg(bias + cc + 1); }
            if (r < NN) {
                float2 o = make_float2(c[i][j][0] + bx, c[i][j][1] + by);
                *(float2*)(out + (size_t)r * OD + cc) = o;
            }
            if (r + 8 < NN) {
                float2 o = make_float2(c[i][j][2] + bx, c[i][j][3] + by);
                *(float2*)(out + (size_t)(r + 8) * OD + cc) = o;
            }
        }
    }
}

// ---------------- el/er = <ft[n,h,:], al/ar[h,:]>; also init m, s ----------------
template<int F>
__global__ void elr_kernel(const float* __restrict__ al, const float* __restrict__ ar)
{
    int i = blockIdx.x * blockDim.x + threadIdx.x;   // over N*H
    if (i >= NN * 4) return;
    int h = i & 3;
    const float* f = g_ft + (size_t)(i >> 2) * (4 * F) + h * F;
    float a = 0.f, b = 0.f;
#pragma unroll
    for (int j = 0; j < F; j++) {
        float v = f[j];
        a += v * __ldg(al + h * F + j);
        b += v * __ldg(ar + h * F + j);
    }
    g_el[i] = a;
    g_er[i] = b;
    g_m[i]  = -FLT_MAX;
    g_s[i]  = 0.f;
}

// ---------------- edge pass A: compute + store logits, segment max ----------------
__global__ void edge_max_kernel(const int* __restrict__ src, const int* __restrict__ dst)
{
    int e = blockIdx.x * blockDim.x + threadIdx.x;
    if (e >= EE) return;
    int sn = src[e], dn = dst[e];
    float4 l = *(const float4*)(g_el + (size_t)sn * 4);
    float4 r = *(const float4*)(g_er + (size_t)dn * 4);
    float4 ev;
    ev.x = lrelu(l.x + r.x);
    ev.y = lrelu(l.y + r.y);
    ev.z = lrelu(l.z + r.z);
    ev.w = lrelu(l.w + r.w);
    *(float4*)(g_ex + (size_t)e * 4) = ev;          // stash logits for pass B
    float* mp = g_m + (size_t)dn * 4;
    atomicMaxF(mp + 0, ev.x);
    atomicMaxF(mp + 1, ev.y);
    atomicMaxF(mp + 2, ev.z);
    atomicMaxF(mp + 3, ev.w);
}

// ---------------- edge pass B: ex = exp(e - m[dst]); s += ex ----------------
__global__ void edge_sum_kernel(const int* __restrict__ dst)
{
    int e = blockIdx.x * blockDim.x + threadIdx.x;
    if (e >= EE) return;
    int dn = dst[e];
    float4 ev = *(const float4*)(g_ex + (size_t)e * 4);
    float4 m  = *(const float4*)(g_m  + (size_t)dn * 4);
    float4 ex;
    ex.x = expf(ev.x - m.x);
    ex.y = expf(ev.y - m.y);
    ex.z = expf(ev.z - m.z);
    ex.w = expf(ev.w - m.w);
    *(float4*)(g_ex + (size_t)e * 4) = ex;
    float* sp = g_s + (size_t)dn * 4;
    atomicAdd(sp + 0, ex.x);
    atomicAdd(sp + 1, ex.y);
    atomicAdd(sp + 2, ex.z);
    atomicAdd(sp + 3, ex.w);
}

// ---------------- edge pass C: rst[dst] += a * ft[src] (warp per edge) ----------------
template<int OD, int F>
__global__ void edge_aggr_kernel(const int* __restrict__ src, const int* __restrict__ dst)
{
    int w = (blockIdx.x * blockDim.x + threadIdx.x) >> 5;
    if (w >= EE) return;
    int lane = threadIdx.x & 31;
    int sn = __ldg(src + w), dn = __ldg(dst + w);
    float4 ex = *(const float4*)(g_ex + (size_t)w * 4);
    float4 sv = *(const float4*)(g_s  + (size_t)dn * 4);
    float a[4] = { ex.x / sv.x, ex.y / sv.y, ex.z / sv.z, ex.w / sv.w };
    const float4* fp = (const float4*)(g_ft + (size_t)sn * OD);
    float* rp = g_rst + (size_t)dn * OD;
#pragma unroll
    for (int j4 = lane; j4 < OD / 4; j4 += 32) {
        float4 f = fp[j4];
        float av = a[(j4 * 4) / F];
        asm volatile("red.global.add.v4.f32 [%0], {%1,%2,%3,%4};"
                     :: "l"(rp + j4 * 4),
                        "f"(f.x * av), "f"(f.y * av), "f"(f.z * av), "f"(f.w * av)
                     : "memory");
    }
}

// ---------------- batchnorm ----------------
__global__ void bn_init_kernel()
{
    int t = threadIdx.x;
    if (t < 128) { g_bnsum[t] = 0.f; g_bnsq[t] = 0.f; }
}

__global__ void bn_stats_kernel(const float* __restrict__ x)
{
    __shared__ float ss[256], sq[256];
    int c    = threadIdx.x & 127;
    int half = threadIdx.x >> 7;
    int r0   = blockIdx.x * 256 + half;
    int rend = min(NN, (int)(blockIdx.x + 1) * 256);
    float s = 0.f, q = 0.f;
    for (int r = r0; r < rend; r += 2) {
        float v = x[(size_t)r * 128 + c];
        s += v; q += v * v;
    }
    ss[threadIdx.x] = s; sq[threadIdx.x] = q;
    __syncthreads();
    if (threadIdx.x < 128) {
        atomicAdd(&g_bnsum[c], ss[c] + ss[c + 128]);
        atomicAdd(&g_bnsq[c],  sq[c] + sq[c + 128]);
    }
}

__global__ void bn_apply_kernel(const float* __restrict__ x, const float* __restrict__ gam,
                                const float* __restrict__ be, float* __restrict__ out)
{
    int i = blockIdx.x * blockDim.x + threadIdx.x;
    if (i >= NN * 128) return;
    int c = i & 127;
    const float invN = 1.f / (float)NN;
    float mean = g_bnsum[c] * invN;
    float var  = g_bnsq[c] * invN - mean * mean;
    float v = (x[i] - mean) * rsqrtf(var + 1e-5f) * __ldg(gam + c) + __ldg(be + c);
    out[i] = fmaxf(v, 0.f);
}

// ---------------- final: mean over heads + bias, log_softmax (warp per node) ----------------
__global__ void final_kernel(const float* __restrict__ bias_last, float* __restrict__ out)
{
    int gw = (blockIdx.x * blockDim.x + threadIdx.x) >> 5;
    if (gw >= NN) return;
    int lane = threadIdx.x & 31;
    const float* r = g_rst + (size_t)gw * 160;

    float v0 = 0.25f * (r[lane] + r[40 + lane] + r[80 + lane] + r[120 + lane])
             + __ldg(bias_last + lane);
    float v1 = -FLT_MAX;
    if (lane < 8) {
        int c1 = lane + 32;
        v1 = 0.25f * (r[c1] + r[40 + c1] + r[80 + c1] + r[120 + c1])
           + __ldg(bias_last + c1);
    }
    float mx = fmaxf(v0, v1);
#pragma unroll
    for (int o = 16; o; o >>= 1) mx = fmaxf(mx, __shfl_xor_sync(0xffffffffu, mx, o));
    float se = expf(v0 - mx) + (lane < 8 ? expf(v1 - mx) : 0.f);
#pragma unroll
    for (int o = 16; o; o >>= 1) se += __shfl_xor_sync(0xffffffffu, se, o);
    float lse = logf(se);
    out[(size_t)gw * 40 + lane] = v0 - mx - lse;
    if (lane < 8) out[(size_t)gw * 40 + lane + 32] = v1 - mx - lse;
}

// ---------------- launch ----------------
extern "C" void kernel_launch(void* const* d_in, const int* in_sizes, int n_in,
                              void* d_out, int out_size)
{
    (void)in_sizes; (void)n_in; (void)out_size;
    const float* feat   = (const float*)d_in[0];
    const int*   src    = (const int*)  d_in[1];
    const int*   dst    = (const int*)  d_in[2];
    const float* w_fc0  = (const float*)d_in[3];
    const float* al0    = (const float*)d_in[4];
    const float* ar0    = (const float*)d_in[5];
    const float* b0     = (const float*)d_in[6];
    const float* w_lin0 = (const float*)d_in[7];
    const float* gam0   = (const float*)d_in[8];
    const float* be0    = (const float*)d_in[9];
    const float* w_fc1  = (const float*)d_in[10];
    const float* al1    = (const float*)d_in[11];
    const float* ar1    = (const float*)d_in[12];
    const float* b1     = (const float*)d_in[13];
    const float* w_lin1 = (const float*)d_in[14];
    const float* gam1   = (const float*)d_in[15];
    const float* be1    = (const float*)d_in[16];
    const float* w_fc2  = (const float*)d_in[17];
    const float* al2    = (const float*)d_in[18];
    const float* ar2    = (const float*)d_in[19];
    const float* b2     = (const float*)d_in[20];
    const float* w_lin2 = (const float*)d_in[21];
    const float* blast  = (const float*)d_in[22];

    float *ft, *rst, *h;
    cudaGetSymbolAddress((void**)&ft,  g_ft);
    cudaGetSymbolAddress((void**)&rst, g_rst);
    cudaGetSymbolAddress((void**)&h,   g_h);

    const dim3 g128((NN + 127) / 128, 4);
    const dim3 g160((NN + 127) / 128, 5);
    const int EB   = (EE + 255) / 256;
    const int AGGB = (int)(((long long)EE * 32 + 255) / 256);
    const int NHB  = (NN * 4 + 255) / 256;
    const int NEL  = (NN * 128 + 255) / 256;
    const int BNB  = (NN + 255) / 256;
    const int FNB  = (NN * 32 + 255) / 256;

    // ---- layer 0 (in=128, OD=128, F=32) ----
    gemm_tc<128><<<g128, 128>>>(feat, w_fc0, nullptr, ft);
    gemm_tc<128><<<g128, 128>>>(feat, w_lin0, b0, rst);
    elr_kernel<32><<<NHB, 256>>>(al0, ar0);
    edge_max_kernel<<<EB, 256>>>(src, dst);
    edge_sum_kernel<<<EB, 256>>>(dst);
    edge_aggr_kernel<128, 32><<<AGGB, 256>>>(src, dst);
    bn_init_kernel<<<1, 128>>>();
    bn_stats_kernel<<<BNB, 256>>>(rst);
    bn_apply_kernel<<<NEL, 256>>>(rst, gam0, be0, h);

    // ---- layer 1 (in=128, OD=128, F=32) ----
    gemm_tc<128><<<g128, 128>>>(h, w_fc1, nullptr, ft);
    gemm_tc<128><<<g128, 128>>>(h, w_lin1, b1, rst);
    elr_kernel<32><<<NHB, 256>>>(al1, ar1);
    edge_max_kernel<<<EB, 256>>>(src, dst);
    edge_sum_kernel<<<EB, 256>>>(dst);
    edge_aggr_kernel<128, 32><<<AGGB, 256>>>(src, dst);
    bn_init_kernel<<<1, 128>>>();
    bn_stats_kernel<<<BNB, 256>>>(rst);
    bn_apply_kernel<<<NEL, 256>>>(rst, gam1, be1, h);

    // ---- layer 2 (in=128, OD=160, F=40) ----
    gemm_tc<160><<<g160, 128>>>(h, w_fc2, nullptr, ft);
    gemm_tc<160><<<g160, 128>>>(h, w_lin2, b2, rst);
    elr_kernel<40><<<NHB, 256>>>(al2, ar2);
    edge_max_kernel<<<EB, 256>>>(src, dst);
    edge_sum_kernel<<<EB, 256>>>(dst);
    edge_aggr_kernel<160, 40><<<AGGB, 256>>>(src, dst);
    final_kernel<<<FNB, 256>>>(blast, (float*)d_out);
}

// round 7
// speedup vs baseline: 1.1587x; 1.0021x over previous
#include <cuda_runtime.h>
#include <math.h>
#include <float.h>

#define NN 50000
#define EE 800000

// ---------------- persistent scratch (device globals; no allocation) ----------------
__device__ float g_ft [NN * 160];   // per-layer transformed features [N, H*F]
__device__ float g_rst[NN * 160];   // accumulator: skip + bias + messages
__device__ float g_h  [NN * 128];   // activations between layers
__device__ float g_el [NN * 4];
__device__ float g_er [NN * 4];
__device__ float g_m  [NN * 4];     // segment max
__device__ float g_s  [NN * 4];     // segment sum of exp
__device__ float g_ex [EE * 4];     // per-edge logits, then exp(e - m[dst])
__device__ float g_bnsum[128];
__device__ float g_bnsq [128];

__device__ __forceinline__ float lrelu(float x) { return x > 0.f ? x : 0.2f * x; }

__device__ __forceinline__ void atomicMaxF(float* addr, float v) {
    if (v >= 0.f) atomicMax((int*)addr, __float_as_int(v));
    else          atomicMin((unsigned int*)addr, (unsigned int)__float_as_int(v));
}

__device__ __forceinline__ float tf32r(float x) {
    unsigned u;
    asm("cvt.rna.tf32.f32 %0, %1;" : "=r"(u) : "f"(x));
    return __uint_as_float(u);
}

__device__ __forceinline__ void mma_tf32(float* c, const unsigned* a, const unsigned* b) {
    asm volatile(
        "mma.sync.aligned.m16n8k8.row.col.f32.tf32.tf32.f32 "
        "{%0,%1,%2,%3}, {%4,%5,%6,%7}, {%8,%9}, {%0,%1,%2,%3};\n"
        : "+f"(c[0]), "+f"(c[1]), "+f"(c[2]), "+f"(c[3])
        : "r"(a[0]), "r"(a[1]), "r"(a[2]), "r"(a[3]), "r"(b[0]), "r"(b[1]));
}

// ---------------- tf32 tensor-core GEMM: out[n,c] = sum_k X[n,k] W[k,c] (+bias) ----
// K = 128. Block tile 128x32, 4 warps (each 32x32 = 2x4 mma m16n8k8), BK = 32.
// Smem pads of 37 make every fragment load and smem store bank-conflict-free.
template<int OD>
__global__ __launch_bounds__(128)
void gemm_tc(const float* __restrict__ X, const float* __restrict__ W,
             const float* __restrict__ bias, float* __restrict__ out)
{
    __shared__ float As[128 * 37];   // [m][k]
    __shared__ float Bs[32 * 37];    // [n][k]  (transposed on load)
    const int tid  = threadIdx.x;
    const int warp = tid >> 5, lane = tid & 31;
    const int g    = lane >> 2, t = lane & 3;
    const int row0 = blockIdx.x * 128;
    const int col0 = blockIdx.y * 32;

    float c[2][4][4];
#pragma unroll
    for (int i = 0; i < 2; i++)
#pragma unroll
        for (int j = 0; j < 4; j++)
#pragma unroll
            for (int q = 0; q < 4; q++) c[i][j][q] = 0.f;

#pragma unroll
    for (int kb = 0; kb < 128; kb += 32) {
        // A tile: 128 rows x 32 k, float4 coalesced, tf32-rounded into smem
#pragma unroll
        for (int j = 0; j < 8; j++) {
            int i4 = tid + j * 128;          // 0..1023 float4 slots (8 per row)
            int r  = i4 >> 3;
            int k4 = (i4 & 7) << 2;
            float4 v = make_float4(0.f, 0.f, 0.f, 0.f);
            if (row0 + r < NN)
                v = *(const float4*)(X + (size_t)(row0 + r) * 128 + kb + k4);
            float* ap = &As[r * 37 + k4];
            ap[0] = tf32r(v.x); ap[1] = tf32r(v.y); ap[2] = tf32r(v.z); ap[3] = tf32r(v.w);
        }
        // B tile: 32 k x 32 n, transpose into Bs[n][k]
#pragma unroll
        for (int j = 0; j < 2; j++) {
            int i4 = tid + j * 128;          // 0..255 float4 slots
            int k  = i4 >> 3;
            int n4 = (i4 & 7) << 2;
            float4 v = *(const float4*)(W + (size_t)(kb + k) * OD + col0 + n4);
            Bs[(n4 + 0) * 37 + k] = tf32r(v.x);
            Bs[(n4 + 1) * 37 + k] = tf32r(v.y);
            Bs[(n4 + 2) * 37 + k] = tf32r(v.z);
            Bs[(n4 + 3) * 37 + k] = tf32r(v.w);
        }
        __syncthreads();
#pragma unroll
        for (int ks = 0; ks < 4; ks++) {
            const int k0 = ks * 8;
            unsigned a[2][4], b[4][2];
            const int mbase = warp * 32;
#pragma unroll
            for (int i = 0; i < 2; i++) {
                const float* ap = As + (mbase + i * 16 + g) * 37 + k0 + t;
                a[i][0] = __float_as_uint(ap[0]);
                a[i][1] = __float_as_uint(ap[8 * 37]);
                a[i][2] = __float_as_uint(ap[4]);
                a[i][3] = __float_as_uint(ap[8 * 37 + 4]);
            }
#pragma unroll
            for (int j = 0; j < 4; j++) {
                const float* bp = Bs + (j * 8 + g) * 37 + k0 + t;
                b[j][0] = __float_as_uint(bp[0]);
                b[j][1] = __float_as_uint(bp[4]);
            }
#pragma unroll
            for (int i = 0; i < 2; i++)
#pragma unroll
                for (int j = 0; j < 4; j++)
                    mma_tf32(c[i][j], a[i], b[j]);
        }
        __syncthreads();
    }

    // epilogue: c0,c1 -> (row g, col 2t..2t+1); c2,c3 -> (row g+8)
#pragma unroll
    for (int i = 0; i < 2; i++) {
        int r = row0 + warp * 32 + i * 16 + g;
#pragma unroll
        for (int j = 0; j < 4; j++) {
            int cc = col0 + j * 8 + 2 * t;
            float bx = 0.f, by = 0.f;
            if (bias) { bx = __ldg(bias + cc); by = __ldg(bias + cc + 1); }
            if (r < NN) {
                float2 o = make_float2(c[i][j][0] + bx, c[i][j][1] + by);
                *(float2*)(out + (size_t)r * OD + cc) = o;
            }
            if (r + 8 < NN) {
                float2 o = make_float2(c[i][j][2] + bx, c[i][j][3] + by);
                *(float2*)(out + (size_t)(r + 8) * OD + cc) = o;
            }
        }
    }
}

// ---------------- el/er = <ft[n,h,:], al/ar[h,:]>; also init m, s ----------------
template<int F>
__global__ void elr_kernel(const float* __restrict__ al, const float* __restrict__ ar)
{
    int i = blockIdx.x * blockDim.x + threadIdx.x;   // over N*H
    if (i >= NN * 4) return;
    int h = i & 3;
    const float* f = g_ft + (size_t)(i >> 2) * (4 * F) + h * F;
    float a = 0.f, b = 0.f;
#pragma unroll
    for (int j = 0; j < F; j++) {
        float v = f[j];
        a += v * __ldg(al + h * F + j);
        b += v * __ldg(ar + h * F + j);
    }
    g_el[i] = a;
    g_er[i] = b;
    g_m[i]  = -FLT_MAX;
    g_s[i]  = 0.f;
}

// ---------------- edge pass A: compute + store logits, segment max ----------------
__global__ void edge_max_kernel(const int* __restrict__ src, const int* __restrict__ dst)
{
    int e = blockIdx.x * blockDim.x + threadIdx.x;
    if (e >= EE) return;
    int sn = src[e], dn = dst[e];
    float4 l = *(const float4*)(g_el + (size_t)sn * 4);
    float4 r = *(const float4*)(g_er + (size_t)dn * 4);
    float4 ev;
    ev.x = lrelu(l.x + r.x);
    ev.y = lrelu(l.y + r.y);
    ev.z = lrelu(l.z + r.z);
    ev.w = lrelu(l.w + r.w);
    *(float4*)(g_ex + (size_t)e * 4) = ev;          // stash logits for pass B
    float* mp = g_m + (size_t)dn * 4;
    atomicMaxF(mp + 0, ev.x);
    atomicMaxF(mp + 1, ev.y);
    atomicMaxF(mp + 2, ev.z);
    atomicMaxF(mp + 3, ev.w);
}

// ---------------- edge pass B: ex = exp(e - m[dst]); s += ex ----------------
__global__ void edge_sum_kernel(const int* __restrict__ dst)
{
    int e = blockIdx.x * blockDim.x + threadIdx.x;
    if (e >= EE) return;
    int dn = dst[e];
    float4 ev = *(const float4*)(g_ex + (size_t)e * 4);
    float4 m  = *(const float4*)(g_m  + (size_t)dn * 4);
    float4 ex;
    ex.x = expf(ev.x - m.x);
    ex.y = expf(ev.y - m.y);
    ex.z = expf(ev.z - m.z);
    ex.w = expf(ev.w - m.w);
    *(float4*)(g_ex + (size_t)e * 4) = ex;
    float* sp = g_s + (size_t)dn * 4;
    atomicAdd(sp + 0, ex.x);
    atomicAdd(sp + 1, ex.y);
    atomicAdd(sp + 2, ex.z);
    atomicAdd(sp + 3, ex.w);
}

// ---------------- edge pass C: rst[dst] += a * ft[src] (warp per edge) ----------------
template<int OD, int F>
__global__ void edge_aggr_kernel(const int* __restrict__ src, const int* __restrict__ dst)
{
    int w = (blockIdx.x * blockDim.x + threadIdx.x) >> 5;
    if (w >= EE) return;
    int lane = threadIdx.x & 31;
    int sn = __ldg(src + w), dn = __ldg(dst + w);
    float4 ex = *(const float4*)(g_ex + (size_t)w * 4);
    float4 sv = *(const float4*)(g_s  + (size_t)dn * 4);
    float a[4] = { ex.x / sv.x, ex.y / sv.y, ex.z / sv.z, ex.w / sv.w };
    const float4* fp = (const float4*)(g_ft + (size_t)sn * OD);
    float* rp = g_rst + (size_t)dn * OD;
#pragma unroll
    for (int j4 = lane; j4 < OD / 4; j4 += 32) {
        float4 f = fp[j4];
        float av = a[(j4 * 4) / F];
        asm volatile("red.global.add.v4.f32 [%0], {%1,%2,%3,%4};"
                     :: "l"(rp + j4 * 4),
                        "f"(f.x * av), "f"(f.y * av), "f"(f.z * av), "f"(f.w * av)
                     : "memory");
    }
}

// ---------------- batchnorm ----------------
__global__ void bn_init_kernel()
{
    int t = threadIdx.x;
    if (t < 128) { g_bnsum[t] = 0.f; g_bnsq[t] = 0.f; }
}

__global__ void bn_stats_kernel(const float* __restrict__ x)
{
    __shared__ float ss[256], sq[256];
    int c    = threadIdx.x & 127;
    int half = threadIdx.x >> 7;
    int r0   = blockIdx.x * 256 + half;
    int rend = min(NN, (int)(blockIdx.x + 1) * 256);
    float s = 0.f, q = 0.f;
    for (int r = r0; r < rend; r += 2) {
        float v = x[(size_t)r * 128 + c];
        s += v; q += v * v;
    }
    ss[threadIdx.x] = s; sq[threadIdx.x] = q;
    __syncthreads();
    if (threadIdx.x < 128) {
        atomicAdd(&g_bnsum[c], ss[c] + ss[c + 128]);
        atomicAdd(&g_bnsq[c],  sq[c] + sq[c + 128]);
    }
}

__global__ void bn_apply_kernel(const float* __restrict__ x, const float* __restrict__ gam,
                                const float* __restrict__ be, float* __restrict__ out)
{
    int i = blockIdx.x * blockDim.x + threadIdx.x;
    if (i >= NN * 128) return;
    int c = i & 127;
    const float invN = 1.f / (float)NN;
    float mean = g_bnsum[c] * invN;
    float var  = g_bnsq[c] * invN - mean * mean;
    float v = (x[i] - mean) * rsqrtf(var + 1e-5f) * __ldg(gam + c) + __ldg(be + c);
    out[i] = fmaxf(v, 0.f);
}

// ---------------- final: mean over heads + bias, log_softmax (warp per node) ----------------
__global__ void final_kernel(const float* __restrict__ bias_last, float* __restrict__ out)
{
    int gw = (blockIdx.x * blockDim.x + threadIdx.x) >> 5;
    if (gw >= NN) return;
    int lane = threadIdx.x & 31;
    const float* r = g_rst + (size_t)gw * 160;

    float v0 = 0.25f * (r[lane] + r[40 + lane] + r[80 + lane] + r[120 + lane])
             + __ldg(bias_last + lane);
    float v1 = -FLT_MAX;
    if (lane < 8) {
        int c1 = lane + 32;
        v1 = 0.25f * (r[c1] + r[40 + c1] + r[80 + c1] + r[120 + c1])
           + __ldg(bias_last + c1);
    }
    float mx = fmaxf(v0, v1);
#pragma unroll
    for (int o = 16; o; o >>= 1) mx = fmaxf(mx, __shfl_xor_sync(0xffffffffu, mx, o));
    float se = expf(v0 - mx) + (lane < 8 ? expf(v1 - mx) : 0.f);
#pragma unroll
    for (int o = 16; o; o >>= 1) se += __shfl_xor_sync(0xffffffffu, se, o);
    float lse = logf(se);
    out[(size_t)gw * 40 + lane] = v0 - mx - lse;
    if (lane < 8) out[(size_t)gw * 40 + lane + 32] = v1 - mx - lse;
}

// ---------------- launch ----------------
extern "C" void kernel_launch(void* const* d_in, const int* in_sizes, int n_in,
                              void* d_out, int out_size)
{
    (void)in_sizes; (void)n_in; (void)out_size;
    const float* feat   = (const float*)d_in[0];
    const int*   src    = (const int*)  d_in[1];
    const int*   dst    = (const int*)  d_in[2];
    const float* w_fc0  = (const float*)d_in[3];
    const float* al0    = (const float*)d_in[4];
    const float* ar0    = (const float*)d_in[5];
    const float* b0     = (const float*)d_in[6];
    const float* w_lin0 = (const float*)d_in[7];
    const float* gam0   = (const float*)d_in[8];
    const float* be0    = (const float*)d_in[9];
    const float* w_fc1  = (const float*)d_in[10];
    const float* al1    = (const float*)d_in[11];
    const float* ar1    = (const float*)d_in[12];
    const float* b1     = (const float*)d_in[13];
    const float* w_lin1 = (const float*)d_in[14];
    const float* gam1   = (const float*)d_in[15];
    const float* be1    = (const float*)d_in[16];
    const float* w_fc2  = (const float*)d_in[17];
    const float* al2    = (const float*)d_in[18];
    const float* ar2    = (const float*)d_in[19];
    const float* b2     = (const float*)d_in[20];
    const float* w_lin2 = (const float*)d_in[21];
    const float* blast  = (const float*)d_in[22];

    float *ft, *rst, *h;
    cudaGetSymbolAddress((void**)&ft,  g_ft);
    cudaGetSymbolAddress((void**)&rst, g_rst);
    cudaGetSymbolAddress((void**)&h,   g_h);

    const dim3 g128((NN + 127) / 128, 4);
    const dim3 g160((NN + 127) / 128, 5);
    const int EB   = (EE + 255) / 256;
    const int AGGB = (int)(((long long)EE * 32 + 255) / 256);
    const int NHB  = (NN * 4 + 255) / 256;
    const int NEL  = (NN * 128 + 255) / 256;
    const int BNB  = (NN + 255) / 256;
    const int FNB  = (NN * 32 + 255) / 256;

    // ---- layer 0 (in=128, OD=128, F=32) ----
    gemm_tc<128><<<g128, 128>>>(feat, w_fc0, nullptr, ft);
    gemm_tc<128><<<g128, 128>>>(feat, w_lin0, b0, rst);
    elr_kernel<32><<<NHB, 256>>>(al0, ar0);
    edge_max_kernel<<<EB, 256>>>(src, dst);
    edge_sum_kernel<<<EB, 256>>>(dst);
    edge_aggr_kernel<128, 32><<<AGGB, 256>>>(src, dst);
    bn_init_kernel<<<1, 128>>>();
    bn_stats_kernel<<<BNB, 256>>>(rst);
    bn_apply_kernel<<<NEL, 256>>>(rst, gam0, be0, h);

    // ---- layer 1 (in=128, OD=128, F=32) ----
    gemm_tc<128><<<g128, 128>>>(h, w_fc1, nullptr, ft);
    gemm_tc<128><<<g128, 128>>>(h, w_lin1, b1, rst);
    elr_kernel<32><<<NHB, 256>>>(al1, ar1);
    edge_max_kernel<<<EB, 256>>>(src, dst);
    edge_sum_kernel<<<EB, 256>>>(dst);
    edge_aggr_kernel<128, 32><<<AGGB, 256>>>(src, dst);
    bn_init_kernel<<<1, 128>>>();
    bn_stats_kernel<<<BNB, 256>>>(rst);
    bn_apply_kernel<<<NEL, 256>>>(rst, gam1, be1, h);

    // ---- layer 2 (in=128, OD=160, F=40) ----
    gemm_tc<160><<<g160, 128>>>(h, w_fc2, nullptr, ft);
    gemm_tc<160><<<g160, 128>>>(h, w_lin2, b2, rst);
    elr_kernel<40><<<NHB, 256>>>(al2, ar2);
    edge_max_kernel<<<EB, 256>>>(src, dst);
    edge_sum_kernel<<<EB, 256>>>(dst);
    edge_aggr_kernel<160, 40><<<AGGB, 256>>>(src, dst);
    final_kernel<<<FNB, 256>>>(blast, (float*)d_out);
}

// round 8
// speedup vs baseline: 1.5361x; 1.3257x over previous
#include <cuda_runtime.h>
#include <math.h>
#include <float.h>

#define NN 50000
#define EE 800000

// ---------------- persistent scratch (device globals; no allocation) ----------------
__device__ float g_ft [NN * 160];   // per-layer transformed features [N, H*F]
__device__ float g_rst[NN * 160];   // accumulator: skip + bias + messages
__device__ float g_h  [NN * 128];   // activations between layers
__device__ float g_el [NN * 4];
__device__ float g_er [NN * 4];
__device__ float g_ex [EE * 4];     // per-edge exp(e - m) (CSR order)
__device__ int   g_rowptr[NN + 1];
__device__ int   g_tmp   [NN];      // counts, then running offsets for scatter
__device__ int   g_csr_src[EE];     // src node per edge, sorted by dst
__device__ float g_bnsum[128];
__device__ float g_bnsq [128];

__device__ __forceinline__ float lrelu(float x) { return x > 0.f ? x : 0.2f * x; }

__device__ __forceinline__ float tf32r(float x) {
    unsigned u;
    asm("cvt.rna.tf32.f32 %0, %1;" : "=r"(u) : "f"(x));
    return __uint_as_float(u);
}

__device__ __forceinline__ void mma_tf32(float* c, const unsigned* a, const unsigned* b) {
    asm volatile(
        "mma.sync.aligned.m16n8k8.row.col.f32.tf32.tf32.f32 "
        "{%0,%1,%2,%3}, {%4,%5,%6,%7}, {%8,%9}, {%0,%1,%2,%3};\n"
        : "+f"(c[0]), "+f"(c[1]), "+f"(c[2]), "+f"(c[3])
        : "r"(a[0]), "r"(a[1]), "r"(a[2]), "r"(a[3]), "r"(b[0]), "r"(b[1]));
}

// ================= CSR build (graph is constant; rebuilt each replay) =================
__global__ void zero_cnt_kernel()
{
    int i = blockIdx.x * blockDim.x + threadIdx.x;
    if (i < NN) g_tmp[i] = 0;
}

__global__ void hist_kernel(const int* __restrict__ dst)
{
    int e = blockIdx.x * blockDim.x + threadIdx.x;
    if (e < EE) atomicAdd(&g_tmp[dst[e]], 1);
}

// single-block exclusive scan of g_tmp (counts) -> g_rowptr & g_tmp (offsets)
__global__ __launch_bounds__(1024) void scan_kernel()
{
    __shared__ int warp_sums[32];
    __shared__ int s_carry;
    const int t = threadIdx.x, lane = t & 31, wid = t >> 5;
    if (t == 0) s_carry = 0;
    __syncthreads();
    for (int base = 0; base < NN; base += 1024) {
        int idx = base + t;
        int v = (idx < NN) ? g_tmp[idx] : 0;
        int x = v;
#pragma unroll
        for (int o = 1; o < 32; o <<= 1) {
            int y = __shfl_up_sync(0xffffffffu, x, o);
            if (lane >= o) x += y;
        }
        if (lane == 31) warp_sums[wid] = x;
        __syncthreads();
        if (wid == 0) {
            int w = warp_sums[lane];
#pragma unroll
            for (int o = 1; o < 32; o <<= 1) {
                int y = __shfl_up_sync(0xffffffffu, w, o);
                if (lane >= o) w += y;
            }
            warp_sums[lane] = w;
        }
        __syncthreads();
        int excl = (x - v) + (wid ? warp_sums[wid - 1] : 0) + s_carry;
        if (idx < NN) { g_rowptr[idx] = excl; g_tmp[idx] = excl; }
        __syncthreads();
        if (t == 0) s_carry += warp_sums[31];
        __syncthreads();
    }
    if (threadIdx.x == 0) g_rowptr[NN] = s_carry;
}

__global__ void scatter_kernel(const int* __restrict__ src, const int* __restrict__ dst)
{
    int e = blockIdx.x * blockDim.x + threadIdx.x;
    if (e >= EE) return;
    int pos = atomicAdd(&g_tmp[dst[e]], 1);
    g_csr_src[pos] = src[e];
}

// ---------------- tf32 tensor-core GEMM: out[n,c] = sum_k X[n,k] W[k,c] (+bias) ----
template<int OD>
__global__ __launch_bounds__(128)
void gemm_tc(const float* __restrict__ X, const float* __restrict__ W,
             const float* __restrict__ bias, float* __restrict__ out)
{
    __shared__ float As[128 * 37];   // [m][k]
    __shared__ float Bs[32 * 37];    // [n][k]  (transposed on load)
    const int tid  = threadIdx.x;
    const int warp = tid >> 5, lane = tid & 31;
    const int g    = lane >> 2, t = lane & 3;
    const int row0 = blockIdx.x * 128;
    const int col0 = blockIdx.y * 32;

    float c[2][4][4];
#pragma unroll
    for (int i = 0; i < 2; i++)
#pragma unroll
        for (int j = 0; j < 4; j++)
#pragma unroll
            for (int q = 0; q < 4; q++) c[i][j][q] = 0.f;

#pragma unroll
    for (int kb = 0; kb < 128; kb += 32) {
#pragma unroll
        for (int j = 0; j < 8; j++) {
            int i4 = tid + j * 128;
            int r  = i4 >> 3;
            int k4 = (i4 & 7) << 2;
            float4 v = make_float4(0.f, 0.f, 0.f, 0.f);
            if (row0 + r < NN)
                v = *(const float4*)(X + (size_t)(row0 + r) * 128 + kb + k4);
            float* ap = &As[r * 37 + k4];
            ap[0] = tf32r(v.x); ap[1] = tf32r(v.y); ap[2] = tf32r(v.z); ap[3] = tf32r(v.w);
        }
#pragma unroll
        for (int j = 0; j < 2; j++) {
            int i4 = tid + j * 128;
            int k  = i4 >> 3;
            int n4 = (i4 & 7) << 2;
            float4 v = *(const float4*)(W + (size_t)(kb + k) * OD + col0 + n4);
            Bs[(n4 + 0) * 37 + k] = tf32r(v.x);
            Bs[(n4 + 1) * 37 + k] = tf32r(v.y);
            Bs[(n4 + 2) * 37 + k] = tf32r(v.z);
            Bs[(n4 + 3) * 37 + k] = tf32r(v.w);
        }
        __syncthreads();
#pragma unroll
        for (int ks = 0; ks < 4; ks++) {
            const int k0 = ks * 8;
            unsigned a[2][4], b[4][2];
            const int mbase = warp * 32;
#pragma unroll
            for (int i = 0; i < 2; i++) {
                const float* ap = As + (mbase + i * 16 + g) * 37 + k0 + t;
                a[i][0] = __float_as_uint(ap[0]);
                a[i][1] = __float_as_uint(ap[8 * 37]);
                a[i][2] = __float_as_uint(ap[4]);
                a[i][3] = __float_as_uint(ap[8 * 37 + 4]);
            }
#pragma unroll
            for (int j = 0; j < 4; j++) {
                const float* bp = Bs + (j * 8 + g) * 37 + k0 + t;
                b[j][0] = __float_as_uint(bp[0]);
                b[j][1] = __float_as_uint(bp[4]);
            }
#pragma unroll
            for (int i = 0; i < 2; i++)
#pragma unroll
                for (int j = 0; j < 4; j++)
                    mma_tf32(c[i][j], a[i], b[j]);
        }
        __syncthreads();
    }

#pragma unroll
    for (int i = 0; i < 2; i++) {
        int r = row0 + warp * 32 + i * 16 + g;
#pragma unroll
        for (int j = 0; j < 4; j++) {
            int cc = col0 + j * 8 + 2 * t;
            float bx = 0.f, by = 0.f;
            if (bias) { bx = __ldg(bias + cc); by = __ldg(bias + cc + 1); }
            if (r < NN) {
                float2 o = make_float2(c[i][j][0] + bx, c[i][j][1] + by);
                *(float2*)(out + (size_t)r * OD + cc) = o;
            }
            if (r + 8 < NN) {
                float2 o = make_float2(c[i][j][2] + bx, c[i][j][3] + by);
                *(float2*)(out + (size_t)(r + 8) * OD + cc) = o;
            }
        }
    }
}

// ---------------- el/er = <ft[n,h,:], al/ar[h,:]> ----------------
template<int F>
__global__ void elr_kernel(const float* __restrict__ al, const float* __restrict__ ar)
{
    int i = blockIdx.x * blockDim.x + threadIdx.x;   // over N*H
    if (i >= NN * 4) return;
    int h = i & 3;
    const float* f = g_ft + (size_t)(i >> 2) * (4 * F) + h * F;
    float a = 0.f, b = 0.f;
#pragma unroll
    for (int j = 0; j < F; j++) {
        float v = f[j];
        a += v * __ldg(al + h * F + j);
        b += v * __ldg(ar + h * F + j);
    }
    g_el[i] = a;
    g_er[i] = b;
}

// ================= fused per-dst-node softmax + aggregation (warp per node) =========
// rst[dn] (already holds skip+bias) += sum_e softmax(e) * ft[src_e]
template<int OD, int F>
__global__ __launch_bounds__(256)
void gat_node_kernel()
{
    const int wn = (blockIdx.x * 256 + threadIdx.x) >> 5;
    if (wn >= NN) return;
    const int lane = threadIdx.x & 31;
    const int beg = g_rowptr[wn], end = g_rowptr[wn + 1];
    const float4 er = *(const float4*)(g_er + (size_t)wn * 4);

    // ---- phase 1: per-head max over incident edges ----
    float4 m = make_float4(-FLT_MAX, -FLT_MAX, -FLT_MAX, -FLT_MAX);
    for (int i = beg + lane; i < end; i += 32) {
        int sn = g_csr_src[i];
        float4 l = *(const float4*)(g_el + (size_t)sn * 4);
        m.x = fmaxf(m.x, lrelu(l.x + er.x));
        m.y = fmaxf(m.y, lrelu(l.y + er.y));
        m.z = fmaxf(m.z, lrelu(l.z + er.z));
        m.w = fmaxf(m.w, lrelu(l.w + er.w));
    }
#pragma unroll
    for (int o = 16; o; o >>= 1) {
        m.x = fmaxf(m.x, __shfl_xor_sync(0xffffffffu, m.x, o));
        m.y = fmaxf(m.y, __shfl_xor_sync(0xffffffffu, m.y, o));
        m.z = fmaxf(m.z, __shfl_xor_sync(0xffffffffu, m.z, o));
        m.w = fmaxf(m.w, __shfl_xor_sync(0xffffffffu, m.w, o));
    }

    // ---- phase 2: exp + per-head sum; stash exp per edge ----
    float4 s = make_float4(0.f, 0.f, 0.f, 0.f);
    for (int i = beg + lane; i < end; i += 32) {
        int sn = g_csr_src[i];             // L2-hit (re-read)
        float4 l = *(const float4*)(g_el + (size_t)sn * 4);
        float4 ex;
        ex.x = __expf(lrelu(l.x + er.x) - m.x);
        ex.y = __expf(lrelu(l.y + er.y) - m.y);
        ex.z = __expf(lrelu(l.z + er.z) - m.z);
        ex.w = __expf(lrelu(l.w + er.w) - m.w);
        *(float4*)(g_ex + (size_t)i * 4) = ex;
        s.x += ex.x; s.y += ex.y; s.z += ex.z; s.w += ex.w;
    }
#pragma unroll
    for (int o = 16; o; o >>= 1) {
        s.x += __shfl_xor_sync(0xffffffffu, s.x, o);
        s.y += __shfl_xor_sync(0xffffffffu, s.y, o);
        s.z += __shfl_xor_sync(0xffffffffu, s.z, o);
        s.w += __shfl_xor_sync(0xffffffffu, s.w, o);
    }
    float4 inv = make_float4(1.f / s.x, 1.f / s.y, 1.f / s.z, 1.f / s.w);

    // ---- phase 3: aggregate msg = a * ft[src]; lane owns float4 column(s) ----
    constexpr int NR = (OD / 4 + 31) / 32;
    float4 acc[NR];
    float  invh[NR];
    int    headr[NR];
#pragma unroll
    for (int rep = 0; rep < NR; rep++) {
        acc[rep] = make_float4(0.f, 0.f, 0.f, 0.f);
        int j4 = lane + rep * 32;
        int h  = (j4 * 4) / F;
        headr[rep] = h;
        invh[rep]  = (h == 0) ? inv.x : (h == 1) ? inv.y : (h == 2) ? inv.z : inv.w;
    }
    for (int i = beg; i < end; i++) {
        int sn = g_csr_src[i];
        float4 exv = *(const float4*)(g_ex + (size_t)i * 4);
#pragma unroll
        for (int rep = 0; rep < NR; rep++) {
            int j4 = lane + rep * 32;
            if (j4 < OD / 4) {
                int h = headr[rep];
                float a = ((h == 0) ? exv.x : (h == 1) ? exv.y : (h == 2) ? exv.z : exv.w)
                        * invh[rep];
                float4 f = *(const float4*)(g_ft + (size_t)sn * OD + j4 * 4);
                acc[rep].x += a * f.x;
                acc[rep].y += a * f.y;
                acc[rep].z += a * f.z;
                acc[rep].w += a * f.w;
            }
        }
    }
#pragma unroll
    for (int rep = 0; rep < NR; rep++) {
        int j4 = lane + rep * 32;
        if (j4 < OD / 4) {
            float* rp = g_rst + (size_t)wn * OD + j4 * 4;
            float4 r = *(const float4*)rp;
            r.x += acc[rep].x; r.y += acc[rep].y; r.z += acc[rep].z; r.w += acc[rep].w;
            *(float4*)rp = r;
        }
    }
}

// ---------------- batchnorm ----------------
__global__ void bn_init_kernel()
{
    int t = threadIdx.x;
    if (t < 128) { g_bnsum[t] = 0.f; g_bnsq[t] = 0.f; }
}

__global__ void bn_stats_kernel(const float* __restrict__ x)
{
    __shared__ float ss[256], sq[256];
    int c    = threadIdx.x & 127;
    int half = threadIdx.x >> 7;
    int r0   = blockIdx.x * 256 + half;
    int rend = min(NN, (int)(blockIdx.x + 1) * 256);
    float s = 0.f, q = 0.f;
    for (int r = r0; r < rend; r += 2) {
        float v = x[(size_t)r * 128 + c];
        s += v; q += v * v;
    }
    ss[threadIdx.x] = s; sq[threadIdx.x] = q;
    __syncthreads();
    if (threadIdx.x < 128) {
        atomicAdd(&g_bnsum[c], ss[c] + ss[c + 128]);
        atomicAdd(&g_bnsq[c],  sq[c] + sq[c + 128]);
    }
}

__global__ void bn_apply_kernel(const float* __restrict__ x, const float* __restrict__ gam,
                                const float* __restrict__ be, float* __restrict__ out)
{
    int i = blockIdx.x * blockDim.x + threadIdx.x;
    if (i >= NN * 128) return;
    int c = i & 127;
    const float invN = 1.f / (float)NN;
    float mean = g_bnsum[c] * invN;
    float var  = g_bnsq[c] * invN - mean * mean;
    float v = (x[i] - mean) * rsqrtf(var + 1e-5f) * __ldg(gam + c) + __ldg(be + c);
    out[i] = fmaxf(v, 0.f);
}

// ---------------- final: mean over heads + bias, log_softmax (warp per node) ----------------
__global__ void final_kernel(const float* __restrict__ bias_last, float* __restrict__ out)
{
    int gw = (blockIdx.x * blockDim.x + threadIdx.x) >> 5;
    if (gw >= NN) return;
    int lane = threadIdx.x & 31;
    const float* r = g_rst + (size_t)gw * 160;

    float v0 = 0.25f * (r[lane] + r[40 + lane] + r[80 + lane] + r[120 + lane])
             + __ldg(bias_last + lane);
    float v1 = -FLT_MAX;
    if (lane < 8) {
        int c1 = lane + 32;
        v1 = 0.25f * (r[c1] + r[40 + c1] + r[80 + c1] + r[120 + c1])
           + __ldg(bias_last + c1);
    }
    float mx = fmaxf(v0, v1);
#pragma unroll
    for (int o = 16; o; o >>= 1) mx = fmaxf(mx, __shfl_xor_sync(0xffffffffu, mx, o));
    float se = expf(v0 - mx) + (lane < 8 ? expf(v1 - mx) : 0.f);
#pragma unroll
    for (int o = 16; o; o >>= 1) se += __shfl_xor_sync(0xffffffffu, se, o);
    float lse = logf(se);
    out[(size_t)gw * 40 + lane] = v0 - mx - lse;
    if (lane < 8) out[(size_t)gw * 40 + lane + 32] = v1 - mx - lse;
}

// ---------------- launch ----------------
extern "C" void kernel_launch(void* const* d_in, const int* in_sizes, int n_in,
                              void* d_out, int out_size)
{
    (void)in_sizes; (void)n_in; (void)out_size;
    const float* feat   = (const float*)d_in[0];
    const int*   src    = (const int*)  d_in[1];
    const int*   dst    = (const int*)  d_in[2];
    const float* w_fc0  = (const float*)d_in[3];
    const float* al0    = (const float*)d_in[4];
    const float* ar0    = (const float*)d_in[5];
    const float* b0     = (const float*)d_in[6];
    const float* w_lin0 = (const float*)d_in[7];
    const float* gam0   = (const float*)d_in[8];
    const float* be0    = (const float*)d_in[9];
    const float* w_fc1  = (const float*)d_in[10];
    const float* al1    = (const float*)d_in[11];
    const float* ar1    = (const float*)d_in[12];
    const float* b1     = (const float*)d_in[13];
    const float* w_lin1 = (const float*)d_in[14];
    const float* gam1   = (const float*)d_in[15];
    const float* be1    = (const float*)d_in[16];
    const float* w_fc2  = (const float*)d_in[17];
    const float* al2    = (const float*)d_in[18];
    const float* ar2    = (const float*)d_in[19];
    const float* b2     = (const float*)d_in[20];
    const float* w_lin2 = (const float*)d_in[21];
    const float* blast  = (const float*)d_in[22];

    float *ft, *rst, *h;
    cudaGetSymbolAddress((void**)&ft,  g_ft);
    cudaGetSymbolAddress((void**)&rst, g_rst);
    cudaGetSymbolAddress((void**)&h,   g_h);

    const dim3 g128((NN + 127) / 128, 4);
    const dim3 g160((NN + 127) / 128, 5);
    const int EB   = (EE + 255) / 256;
    const int NB   = (NN + 255) / 256;
    const int NODB = (NN * 32 + 255) / 256;   // warp per node
    const int NHB  = (NN * 4 + 255) / 256;
    const int NEL  = (NN * 128 + 255) / 256;
    const int BNB  = (NN + 255) / 256;

    // ---- CSR build (graph constant) ----
    zero_cnt_kernel<<<NB, 256>>>();
    hist_kernel<<<EB, 256>>>(dst);
    scan_kernel<<<1, 1024>>>();
    scatter_kernel<<<EB, 256>>>(src, dst);

    // ---- layer 0 (in=128, OD=128, F=32) ----
    gemm_tc<128><<<g128, 128>>>(feat, w_fc0, nullptr, ft);
    gemm_tc<128><<<g128, 128>>>(feat, w_lin0, b0, rst);
    elr_kernel<32><<<NHB, 256>>>(al0, ar0);
    gat_node_kernel<128, 32><<<NODB, 256>>>();
    bn_init_kernel<<<1, 128>>>();
    bn_stats_kernel<<<BNB, 256>>>(rst);
    bn_apply_kernel<<<NEL, 256>>>(rst, gam0, be0, h);

    // ---- layer 1 (in=128, OD=128, F=32) ----
    gemm_tc<128><<<g128, 128>>>(h, w_fc1, nullptr, ft);
    gemm_tc<128><<<g128, 128>>>(h, w_lin1, b1, rst);
    elr_kernel<32><<<NHB, 256>>>(al1, ar1);
    gat_node_kernel<128, 32><<<NODB, 256>>>();
    bn_init_kernel<<<1, 128>>>();
    bn_stats_kernel<<<BNB, 256>>>(rst);
    bn_apply_kernel<<<NEL, 256>>>(rst, gam1, be1, h);

    // ---- layer 2 (in=128, OD=160, F=40) ----
    gemm_tc<160><<<g160, 128>>>(h, w_fc2, nullptr, ft);
    gemm_tc<160><<<g160, 128>>>(h, w_lin2, b2, rst);
    elr_kernel<40><<<NHB, 256>>>(al2, ar2);
    gat_node_kernel<160, 40><<<NODB, 256>>>();
    final_kernel<<<NODB, 256>>>(blast, (float*)d_out);
}

// round 9
// speedup vs baseline: 1.5372x; 1.0008x over previous
#include <cuda_runtime.h>
#include <math.h>
#include <float.h>

#define NN 50000
#define EE 800000

// ---------------- persistent scratch (device globals; no allocation) ----------------
__device__ float g_ft [NN * 160];   // per-layer transformed features [N, H*F]
__device__ float g_rst[NN * 160];   // accumulator: skip + bias + messages
__device__ float g_h  [NN * 128];   // activations between layers
__device__ float g_el [NN * 4];
__device__ float g_er [NN * 4];
__device__ float g_ex [EE * 4];     // per-edge exp(e - m) (CSR order)
__device__ int   g_rowptr[NN + 1];
__device__ int   g_tmp   [NN];      // counts, then running offsets for scatter
__device__ int   g_csr_src[EE];     // src node per edge, sorted by dst
__device__ float g_bnsum[128];
__device__ float g_bnsq [128];

__device__ __forceinline__ float lrelu(float x) { return x > 0.f ? x : 0.2f * x; }

__device__ __forceinline__ float tf32r(float x) {
    unsigned u;
    asm("cvt.rna.tf32.f32 %0, %1;" : "=r"(u) : "f"(x));
    return __uint_as_float(u);
}

__device__ __forceinline__ void mma_tf32(float* c, const unsigned* a, const unsigned* b) {
    asm volatile(
        "mma.sync.aligned.m16n8k8.row.col.f32.tf32.tf32.f32 "
        "{%0,%1,%2,%3}, {%4,%5,%6,%7}, {%8,%9}, {%0,%1,%2,%3};\n"
        : "+f"(c[0]), "+f"(c[1]), "+f"(c[2]), "+f"(c[3])
        : "r"(a[0]), "r"(a[1]), "r"(a[2]), "r"(a[3]), "r"(b[0]), "r"(b[1]));
}

// ================= CSR build (graph is constant; rebuilt each replay) =================
__global__ void zero_cnt_kernel()
{
    int i = blockIdx.x * blockDim.x + threadIdx.x;
    if (i < NN) g_tmp[i] = 0;
}

__global__ void hist_kernel(const int* __restrict__ dst)
{
    int e = blockIdx.x * blockDim.x + threadIdx.x;
    if (e < EE) atomicAdd(&g_tmp[dst[e]], 1);
}

// single-block exclusive scan of g_tmp (counts) -> g_rowptr & g_tmp (offsets)
__global__ __launch_bounds__(1024) void scan_kernel()
{
    __shared__ int warp_sums[32];
    __shared__ int s_carry;
    const int t = threadIdx.x, lane = t & 31, wid = t >> 5;
    if (t == 0) s_carry = 0;
    __syncthreads();
    for (int base = 0; base < NN; base += 1024) {
        int idx = base + t;
        int v = (idx < NN) ? g_tmp[idx] : 0;
        int x = v;
#pragma unroll
        for (int o = 1; o < 32; o <<= 1) {
            int y = __shfl_up_sync(0xffffffffu, x, o);
            if (lane >= o) x += y;
        }
        if (lane == 31) warp_sums[wid] = x;
        __syncthreads();
        if (wid == 0) {
            int w = warp_sums[lane];
#pragma unroll
            for (int o = 1; o < 32; o <<= 1) {
                int y = __shfl_up_sync(0xffffffffu, w, o);
                if (lane >= o) w += y;
            }
            warp_sums[lane] = w;
        }
        __syncthreads();
        int excl = (x - v) + (wid ? warp_sums[wid - 1] : 0) + s_carry;
        if (idx < NN) { g_rowptr[idx] = excl; g_tmp[idx] = excl; }
        __syncthreads();
        if (t == 0) s_carry += warp_sums[31];
        __syncthreads();
    }
    if (threadIdx.x == 0) g_rowptr[NN] = s_carry;
}

__global__ void scatter_kernel(const int* __restrict__ src, const int* __restrict__ dst)
{
    int e = blockIdx.x * blockDim.x + threadIdx.x;
    if (e >= EE) return;
    int pos = atomicAdd(&g_tmp[dst[e]], 1);
    g_csr_src[pos] = src[e];
}

// ---------------- tf32 tensor-core GEMM: out[n,c] = sum_k X[n,k] W[k,c] (+bias) ----
template<int OD>
__global__ __launch_bounds__(128)
void gemm_tc(const float* __restrict__ X, const float* __restrict__ W,
             const float* __restrict__ bias, float* __restrict__ out)
{
    __shared__ float As[128 * 37];   // [m][k]
    __shared__ float Bs[32 * 37];    // [n][k]  (transposed on load)
    const int tid  = threadIdx.x;
    const int warp = tid >> 5, lane = tid & 31;
    const int g    = lane >> 2, t = lane & 3;
    const int row0 = blockIdx.x * 128;
    const int col0 = blockIdx.y * 32;

    float c[2][4][4];
#pragma unroll
    for (int i = 0; i < 2; i++)
#pragma unroll
        for (int j = 0; j < 4; j++)
#pragma unroll
            for (int q = 0; q < 4; q++) c[i][j][q] = 0.f;

#pragma unroll
    for (int kb = 0; kb < 128; kb += 32) {
#pragma unroll
        for (int j = 0; j < 8; j++) {
            int i4 = tid + j * 128;
            int r  = i4 >> 3;
            int k4 = (i4 & 7) << 2;
            float4 v = make_float4(0.f, 0.f, 0.f, 0.f);
            if (row0 + r < NN)
                v = *(const float4*)(X + (size_t)(row0 + r) * 128 + kb + k4);
            float* ap = &As[r * 37 + k4];
            ap[0] = tf32r(v.x); ap[1] = tf32r(v.y); ap[2] = tf32r(v.z); ap[3] = tf32r(v.w);
        }
#pragma unroll
        for (int j = 0; j < 2; j++) {
            int i4 = tid + j * 128;
            int k  = i4 >> 3;
            int n4 = (i4 & 7) << 2;
            float4 v = *(const float4*)(W + (size_t)(kb + k) * OD + col0 + n4);
            Bs[(n4 + 0) * 37 + k] = tf32r(v.x);
            Bs[(n4 + 1) * 37 + k] = tf32r(v.y);
            Bs[(n4 + 2) * 37 + k] = tf32r(v.z);
            Bs[(n4 + 3) * 37 + k] = tf32r(v.w);
        }
        __syncthreads();
#pragma unroll
        for (int ks = 0; ks < 4; ks++) {
            const int k0 = ks * 8;
            unsigned a[2][4], b[4][2];
            const int mbase = warp * 32;
#pragma unroll
            for (int i = 0; i < 2; i++) {
                const float* ap = As + (mbase + i * 16 + g) * 37 + k0 + t;
                a[i][0] = __float_as_uint(ap[0]);
                a[i][1] = __float_as_uint(ap[8 * 37]);
                a[i][2] = __float_as_uint(ap[4]);
                a[i][3] = __float_as_uint(ap[8 * 37 + 4]);
            }
#pragma unroll
            for (int j = 0; j < 4; j++) {
                const float* bp = Bs + (j * 8 + g) * 37 + k0 + t;
                b[j][0] = __float_as_uint(bp[0]);
                b[j][1] = __float_as_uint(bp[4]);
            }
#pragma unroll
            for (int i = 0; i < 2; i++)
#pragma unroll
                for (int j = 0; j < 4; j++)
                    mma_tf32(c[i][j], a[i], b[j]);
        }
        __syncthreads();
    }

#pragma unroll
    for (int i = 0; i < 2; i++) {
        int r = row0 + warp * 32 + i * 16 + g;
#pragma unroll
        for (int j = 0; j < 4; j++) {
            int cc = col0 + j * 8 + 2 * t;
            float bx = 0.f, by = 0.f;
            if (bias) { bx = __ldg(bias + cc); by = __ldg(bias + cc + 1); }
            if (r < NN) {
                float2 o = make_float2(c[i][j][0] + bx, c[i][j][1] + by);
                *(float2*)(out + (size_t)r * OD + cc) = o;
            }
            if (r + 8 < NN) {
                float2 o = make_float2(c[i][j][2] + bx, c[i][j][3] + by);
                *(float2*)(out + (size_t)(r + 8) * OD + cc) = o;
            }
        }
    }
}

// ---------------- el/er = <ft[n,h,:], al/ar[h,:]> ----------------
template<int F>
__global__ void elr_kernel(const float* __restrict__ al, const float* __restrict__ ar)
{
    int i = blockIdx.x * blockDim.x + threadIdx.x;   // over N*H
    if (i >= NN * 4) return;
    int h = i & 3;
    const float* f = g_ft + (size_t)(i >> 2) * (4 * F) + h * F;
    float a = 0.f, b = 0.f;
#pragma unroll
    for (int j = 0; j < F; j++) {
        float v = f[j];
        a += v * __ldg(al + h * F + j);
        b += v * __ldg(ar + h * F + j);
    }
    g_el[i] = a;
    g_er[i] = b;
}

// ================= fused per-dst-node softmax + aggregation (warp per node) =========
// rst[dn] (already holds skip+bias) += sum_e softmax(e) * ft[src_e]
template<int OD, int F>
__global__ __launch_bounds__(256)
void gat_node_kernel()
{
    const int wn = (blockIdx.x * 256 + threadIdx.x) >> 5;
    if (wn >= NN) return;
    const int lane = threadIdx.x & 31;
    const int beg = g_rowptr[wn], end = g_rowptr[wn + 1];
    const float4 er = *(const float4*)(g_er + (size_t)wn * 4);

    // ---- phase 1: per-head max over incident edges ----
    float4 m = make_float4(-FLT_MAX, -FLT_MAX, -FLT_MAX, -FLT_MAX);
    for (int i = beg + lane; i < end; i += 32) {
        int sn = g_csr_src[i];
        float4 l = *(const float4*)(g_el + (size_t)sn * 4);
        m.x = fmaxf(m.x, lrelu(l.x + er.x));
        m.y = fmaxf(m.y, lrelu(l.y + er.y));
        m.z = fmaxf(m.z, lrelu(l.z + er.z));
        m.w = fmaxf(m.w, lrelu(l.w + er.w));
    }
#pragma unroll
    for (int o = 16; o; o >>= 1) {
        m.x = fmaxf(m.x, __shfl_xor_sync(0xffffffffu, m.x, o));
        m.y = fmaxf(m.y, __shfl_xor_sync(0xffffffffu, m.y, o));
        m.z = fmaxf(m.z, __shfl_xor_sync(0xffffffffu, m.z, o));
        m.w = fmaxf(m.w, __shfl_xor_sync(0xffffffffu, m.w, o));
    }

    // ---- phase 2: exp + per-head sum; stash exp per edge ----
    float4 s = make_float4(0.f, 0.f, 0.f, 0.f);
    for (int i = beg + lane; i < end; i += 32) {
        int sn = g_csr_src[i];             // L2-hit (re-read)
        float4 l = *(const float4*)(g_el + (size_t)sn * 4);
        float4 ex;
        ex.x = __expf(lrelu(l.x + er.x) - m.x);
        ex.y = __expf(lrelu(l.y + er.y) - m.y);
        ex.z = __expf(lrelu(l.z + er.z) - m.z);
        ex.w = __expf(lrelu(l.w + er.w) - m.w);
        *(float4*)(g_ex + (size_t)i * 4) = ex;
        s.x += ex.x; s.y += ex.y; s.z += ex.z; s.w += ex.w;
    }
#pragma unroll
    for (int o = 16; o; o >>= 1) {
        s.x += __shfl_xor_sync(0xffffffffu, s.x, o);
        s.y += __shfl_xor_sync(0xffffffffu, s.y, o);
        s.z += __shfl_xor_sync(0xffffffffu, s.z, o);
        s.w += __shfl_xor_sync(0xffffffffu, s.w, o);
    }
    float4 inv = make_float4(1.f / s.x, 1.f / s.y, 1.f / s.z, 1.f / s.w);

    // ---- phase 3: aggregate msg = a * ft[src]; lane owns float4 column(s) ----
    constexpr int NR = (OD / 4 + 31) / 32;
    float4 acc[NR];
    float  invh[NR];
    int    headr[NR];
#pragma unroll
    for (int rep = 0; rep < NR; rep++) {
        acc[rep] = make_float4(0.f, 0.f, 0.f, 0.f);
        int j4 = lane + rep * 32;
        int h  = (j4 * 4) / F;
        headr[rep] = h;
        invh[rep]  = (h == 0) ? inv.x : (h == 1) ? inv.y : (h == 2) ? inv.z : inv.w;
    }
    for (int i = beg; i < end; i++) {
        int sn = g_csr_src[i];
        float4 exv = *(const float4*)(g_ex + (size_t)i * 4);
#pragma unroll
        for (int rep = 0; rep < NR; rep++) {
            int j4 = lane + rep * 32;
            if (j4 < OD / 4) {
                int h = headr[rep];
                float a = ((h == 0) ? exv.x : (h == 1) ? exv.y : (h == 2) ? exv.z : exv.w)
                        * invh[rep];
                float4 f = *(const float4*)(g_ft + (size_t)sn * OD + j4 * 4);
                acc[rep].x += a * f.x;
                acc[rep].y += a * f.y;
                acc[rep].z += a * f.z;
                acc[rep].w += a * f.w;
            }
        }
    }
#pragma unroll
    for (int rep = 0; rep < NR; rep++) {
        int j4 = lane + rep * 32;
        if (j4 < OD / 4) {
            float* rp = g_rst + (size_t)wn * OD + j4 * 4;
            float4 r = *(const float4*)rp;
            r.x += acc[rep].x; r.y += acc[rep].y; r.z += acc[rep].z; r.w += acc[rep].w;
            *(float4*)rp = r;
        }
    }
}

// ---------------- batchnorm ----------------
__global__ void bn_init_kernel()
{
    int t = threadIdx.x;
    if (t < 128) { g_bnsum[t] = 0.f; g_bnsq[t] = 0.f; }
}

__global__ void bn_stats_kernel(const float* __restrict__ x)
{
    __shared__ float ss[256], sq[256];
    int c    = threadIdx.x & 127;
    int half = threadIdx.x >> 7;
    int r0   = blockIdx.x * 256 + half;
    int rend = min(NN, (int)(blockIdx.x + 1) * 256);
    float s = 0.f, q = 0.f;
    for (int r = r0; r < rend; r += 2) {
        float v = x[(size_t)r * 128 + c];
        s += v; q += v * v;
    }
    ss[threadIdx.x] = s; sq[threadIdx.x] = q;
    __syncthreads();
    if (threadIdx.x < 128) {
        atomicAdd(&g_bnsum[c], ss[c] + ss[c + 128]);
        atomicAdd(&g_bnsq[c],  sq[c] + sq[c + 128]);
    }
}

__global__ void bn_apply_kernel(const float* __restrict__ x, const float* __restrict__ gam,
                                const float* __restrict__ be, float* __restrict__ out)
{
    int i = blockIdx.x * blockDim.x + threadIdx.x;
    if (i >= NN * 128) return;
    int c = i & 127;
    const float invN = 1.f / (float)NN;
    float mean = g_bnsum[c] * invN;
    float var  = g_bnsq[c] * invN - mean * mean;
    float v = (x[i] - mean) * rsqrtf(var + 1e-5f) * __ldg(gam + c) + __ldg(be + c);
    out[i] = fmaxf(v, 0.f);
}

// ---------------- final: mean over heads + bias, log_softmax (warp per node) ----------------
__global__ void final_kernel(const float* __restrict__ bias_last, float* __restrict__ out)
{
    int gw = (blockIdx.x * blockDim.x + threadIdx.x) >> 5;
    if (gw >= NN) return;
    int lane = threadIdx.x & 31;
    const float* r = g_rst + (size_t)gw * 160;

    float v0 = 0.25f * (r[lane] + r[40 + lane] + r[80 + lane] + r[120 + lane])
             + __ldg(bias_last + lane);
    float v1 = -FLT_MAX;
    if (lane < 8) {
        int c1 = lane + 32;
        v1 = 0.25f * (r[c1] + r[40 + c1] + r[80 + c1] + r[120 + c1])
           + __ldg(bias_last + c1);
    }
    float mx = fmaxf(v0, v1);
#pragma unroll
    for (int o = 16; o; o >>= 1) mx = fmaxf(mx, __shfl_xor_sync(0xffffffffu, mx, o));
    float se = expf(v0 - mx) + (lane < 8 ? expf(v1 - mx) : 0.f);
#pragma unroll
    for (int o = 16; o; o >>= 1) se += __shfl_xor_sync(0xffffffffu, se, o);
    float lse = logf(se);
    out[(size_t)gw * 40 + lane] = v0 - mx - lse;
    if (lane < 8) out[(size_t)gw * 40 + lane + 32] = v1 - mx - lse;
}

// ---------------- launch ----------------
extern "C" void kernel_launch(void* const* d_in, const int* in_sizes, int n_in,
                              void* d_out, int out_size)
{
    (void)in_sizes; (void)n_in; (void)out_size;
    const float* feat   = (const float*)d_in[0];
    const int*   src    = (const int*)  d_in[1];
    const int*   dst    = (const int*)  d_in[2];
    const float* w_fc0  = (const float*)d_in[3];
    const float* al0    = (const float*)d_in[4];
    const float* ar0    = (const float*)d_in[5];
    const float* b0     = (const float*)d_in[6];
    const float* w_lin0 = (const float*)d_in[7];
    const float* gam0   = (const float*)d_in[8];
    const float* be0    = (const float*)d_in[9];
    const float* w_fc1  = (const float*)d_in[10];
    const float* al1    = (const float*)d_in[11];
    const float* ar1    = (const float*)d_in[12];
    const float* b1     = (const float*)d_in[13];
    const float* w_lin1 = (const float*)d_in[14];
    const float* gam1   = (const float*)d_in[15];
    const float* be1    = (const float*)d_in[16];
    const float* w_fc2  = (const float*)d_in[17];
    const float* al2    = (const float*)d_in[18];
    const float* ar2    = (const float*)d_in[19];
    const float* b2     = (const float*)d_in[20];
    const float* w_lin2 = (const float*)d_in[21];
    const float* blast  = (const float*)d_in[22];

    float *ft, *rst, *h;
    cudaGetSymbolAddress((void**)&ft,  g_ft);
    cudaGetSymbolAddress((void**)&rst, g_rst);
    cudaGetSymbolAddress((void**)&h,   g_h);

    const dim3 g128((NN + 127) / 128, 4);
    const dim3 g160((NN + 127) / 128, 5);
    const int EB   = (EE + 255) / 256;
    const int NB   = (NN + 255) / 256;
    const int NODB = (NN * 32 + 255) / 256;   // warp per node
    const int NHB  = (NN * 4 + 255) / 256;
    const int NEL  = (NN * 128 + 255) / 256;
    const int BNB  = (NN + 255) / 256;

    // ---- CSR build (graph constant) ----
    zero_cnt_kernel<<<NB, 256>>>();
    hist_kernel<<<EB, 256>>>(dst);
    scan_kernel<<<1, 1024>>>();
    scatter_kernel<<<EB, 256>>>(src, dst);

    // ---- layer 0 (in=128, OD=128, F=32) ----
    gemm_tc<128><<<g128, 128>>>(feat, w_fc0, nullptr, ft);
    gemm_tc<128><<<g128, 128>>>(feat, w_lin0, b0, rst);
    elr_kernel<32><<<NHB, 256>>>(al0, ar0);
    gat_node_kernel<128, 32><<<NODB, 256>>>();
    bn_init_kernel<<<1, 128>>>();
    bn_stats_kernel<<<BNB, 256>>>(rst);
    bn_apply_kernel<<<NEL, 256>>>(rst, gam0, be0, h);

    // ---- layer 1 (in=128, OD=128, F=32) ----
    gemm_tc<128><<<g128, 128>>>(h, w_fc1, nullptr, ft);
    gemm_tc<128><<<g128, 128>>>(h, w_lin1, b1, rst);
    elr_kernel<32><<<NHB, 256>>>(al1, ar1);
    gat_node_kernel<128, 32><<<NODB, 256>>>();
    bn_init_kernel<<<1, 128>>>();
    bn_stats_kernel<<<BNB, 256>>>(rst);
    bn_apply_kernel<<<NEL, 256>>>(rst, gam1, be1, h);

    // ---- layer 2 (in=128, OD=160, F=40) ----
    gemm_tc<160><<<g160, 128>>>(h, w_fc2, nullptr, ft);
    gemm_tc<160><<<g160, 128>>>(h, w_lin2, b2, rst);
    elr_kernel<40><<<NHB, 256>>>(al2, ar2);
    gat_node_kernel<160, 40><<<NODB, 256>>>();
    final_kernel<<<NODB, 256>>>(blast, (float*)d_out);
}

// round 10
// speedup vs baseline: 1.8304x; 1.1907x over previous
#include <cuda_runtime.h>
#include <math.h>
#include <float.h>

#define NN 50000
#define EE 800000
#define NSCAN 49   // 49 * 1024 >= NN

// ---------------- persistent scratch (device globals; no allocation) ----------------
__device__ float g_ft [NN * 160];   // transformed features [N, H*F]
__device__ float g_rst[NN * 160];   // layer output (post message-passing)
__device__ float g_sk [NN * 160];   // skip + bias buffer
__device__ float g_el [NN * 4];
__device__ float g_er [NN * 4];
__device__ float g_ex [EE * 4];     // staging for rare high-degree nodes
__device__ int   g_rowptr[NN + 1];
__device__ int   g_tmp   [NN];
__device__ int   g_bsum  [64];
__device__ int   g_csr_src[EE];
__device__ float g_bnsum[128], g_bnsq[128];
__device__ float g_bna[128],   g_bnb[128];   // BN fused scale/shift

__device__ __forceinline__ float lrelu(float x) { return x > 0.f ? x : 0.2f * x; }

__device__ __forceinline__ float tf32r(float x) {
    unsigned u;
    asm("cvt.rna.tf32.f32 %0, %1;" : "=r"(u) : "f"(x));
    return __uint_as_float(u);
}

__device__ __forceinline__ void mma_tf32(float* c, const unsigned* a, const unsigned* b) {
    asm volatile(
        "mma.sync.aligned.m16n8k8.row.col.f32.tf32.tf32.f32 "
        "{%0,%1,%2,%3}, {%4,%5,%6,%7}, {%8,%9}, {%0,%1,%2,%3};\n"
        : "+f"(c[0]), "+f"(c[1]), "+f"(c[2]), "+f"(c[3])
        : "r"(a[0]), "r"(a[1]), "r"(a[2]), "r"(a[3]), "r"(b[0]), "r"(b[1]));
}

// ================= CSR build =================
__global__ void zero_all_kernel()
{
    int i = blockIdx.x * blockDim.x + threadIdx.x;
    if (i < NN)  g_tmp[i] = 0;
    if (i < 128) { g_bnsum[i] = 0.f; g_bnsq[i] = 0.f; }
}

__global__ void hist_kernel(const int* __restrict__ dst)
{
    int e = blockIdx.x * blockDim.x + threadIdx.x;
    if (e < EE) atomicAdd(&g_tmp[dst[e]], 1);
}

// per-block exclusive scan of g_tmp -> g_rowptr (local), block totals -> g_bsum
__global__ __launch_bounds__(1024) void scan1_kernel()
{
    __shared__ int wsum[32];
    const int t = threadIdx.x, lane = t & 31, wid = t >> 5;
    const int idx = blockIdx.x * 1024 + t;
    int v = (idx < NN) ? g_tmp[idx] : 0;
    int x = v;
#pragma unroll
    for (int o = 1; o < 32; o <<= 1) {
        int y = __shfl_up_sync(0xffffffffu, x, o);
        if (lane >= o) x += y;
    }
    if (lane == 31) wsum[wid] = x;
    __syncthreads();
    if (wid == 0) {
        int w = wsum[lane];
#pragma unroll
        for (int o = 1; o < 32; o <<= 1) {
            int y = __shfl_up_sync(0xffffffffu, w, o);
            if (lane >= o) w += y;
        }
        wsum[lane] = w;
        if (lane == 31) g_bsum[blockIdx.x] = w;   // block total
    }
    __syncthreads();
    int excl = (x - v) + (wid ? wsum[wid - 1] : 0);
    if (idx < NN) g_rowptr[idx] = excl;
}

__global__ void scan2_kernel()   // 1 block, 64 threads: exclusive scan of 49 totals
{
    __shared__ int t0;
    int i = threadIdx.x, lane = i & 31, wid = i >> 5;
    int v = (i < NSCAN) ? g_bsum[i] : 0;
    int x = v;
#pragma unroll
    for (int o = 1; o < 32; o <<= 1) {
        int y = __shfl_up_sync(0xffffffffu, x, o);
        if (lane >= o) x += y;
    }
    if (wid == 0 && lane == 31) t0 = x;
    __syncthreads();
    if (wid == 1) x += t0;
    if (i < NSCAN) g_bsum[i] = x - v;
}

__global__ __launch_bounds__(1024) void scan3_kernel()
{
    int idx = blockIdx.x * 1024 + threadIdx.x;
    if (idx < NN) {
        int v = g_rowptr[idx] + g_bsum[blockIdx.x];
        g_rowptr[idx] = v;
        g_tmp[idx]    = v;
    }
    if (idx == 0) g_rowptr[NN] = EE;
}

__global__ void scatter_kernel(const int* __restrict__ src, const int* __restrict__ dst)
{
    int e = blockIdx.x * blockDim.x + threadIdx.x;
    if (e >= EE) return;
    int pos = atomicAdd(&g_tmp[dst[e]], 1);
    g_csr_src[pos] = src[e];
}

// ---------------- tf32 GEMM, optional fused BN+ReLU on input, optional fused el/er ----
// BN:  x <- relu(a[k]*x + b[k]) applied while loading A tile
// ELR: (OD==128 only) block col tile == one head; epilogue computes el/er for its rows
template<int OD, bool BN, bool ELR>
__global__ __launch_bounds__(128)
void gemm_tc(const float* __restrict__ X, const float* __restrict__ W,
             const float* __restrict__ bias, float* __restrict__ out,
             const float* __restrict__ al, const float* __restrict__ ar)
{
    __shared__ float As[128 * 37];
    __shared__ float Bs[32 * 37];
    __shared__ float s_a[128], s_b[128];
    const int tid  = threadIdx.x;
    const int warp = tid >> 5, lane = tid & 31;
    const int g    = lane >> 2, t = lane & 3;
    const int row0 = blockIdx.x * 128;
    const int col0 = blockIdx.y * 32;
    const int h    = blockIdx.y;            // head (ELR path, OD=128)

    if (BN) {
        if (tid < 128) { s_a[tid] = g_bna[tid]; s_b[tid] = g_bnb[tid]; }
        __syncthreads();
    }

    float c[2][4][4];
#pragma unroll
    for (int i = 0; i < 2; i++)
#pragma unroll
        for (int j = 0; j < 4; j++)
#pragma unroll
            for (int q = 0; q < 4; q++) c[i][j][q] = 0.f;

#pragma unroll
    for (int kb = 0; kb < 128; kb += 32) {
#pragma unroll
        for (int j = 0; j < 8; j++) {
            int i4 = tid + j * 128;
            int r  = i4 >> 3;
            int k4 = (i4 & 7) << 2;
            float4 v = make_float4(0.f, 0.f, 0.f, 0.f);
            if (row0 + r < NN)
                v = *(const float4*)(X + (size_t)(row0 + r) * 128 + kb + k4);
            if (BN) {
                v.x = fmaxf(s_a[kb + k4 + 0] * v.x + s_b[kb + k4 + 0], 0.f);
                v.y = fmaxf(s_a[kb + k4 + 1] * v.y + s_b[kb + k4 + 1], 0.f);
                v.z = fmaxf(s_a[kb + k4 + 2] * v.z + s_b[kb + k4 + 2], 0.f);
                v.w = fmaxf(s_a[kb + k4 + 3] * v.w + s_b[kb + k4 + 3], 0.f);
            }
            float* ap = &As[r * 37 + k4];
            ap[0] = tf32r(v.x); ap[1] = tf32r(v.y); ap[2] = tf32r(v.z); ap[3] = tf32r(v.w);
        }
#pragma unroll
        for (int j = 0; j < 2; j++) {
            int i4 = tid + j * 128;
            int k  = i4 >> 3;
            int n4 = (i4 & 7) << 2;
            float4 v = *(const float4*)(W + (size_t)(kb + k) * OD + col0 + n4);
            Bs[(n4 + 0) * 37 + k] = tf32r(v.x);
            Bs[(n4 + 1) * 37 + k] = tf32r(v.y);
            Bs[(n4 + 2) * 37 + k] = tf32r(v.z);
            Bs[(n4 + 3) * 37 + k] = tf32r(v.w);
        }
        __syncthreads();
#pragma unroll
        for (int ks = 0; ks < 4; ks++) {
            const int k0 = ks * 8;
            unsigned a[2][4], b[4][2];
            const int mbase = warp * 32;
#pragma unroll
            for (int i = 0; i < 2; i++) {
                const float* ap = As + (mbase + i * 16 + g) * 37 + k0 + t;
                a[i][0] = __float_as_uint(ap[0]);
                a[i][1] = __float_as_uint(ap[8 * 37]);
                a[i][2] = __float_as_uint(ap[4]);
                a[i][3] = __float_as_uint(ap[8 * 37 + 4]);
            }
#pragma unroll
            for (int j = 0; j < 4; j++) {
                const float* bp = Bs + (j * 8 + g) * 37 + k0 + t;
                b[j][0] = __float_as_uint(bp[0]);
                b[j][1] = __float_as_uint(bp[4]);
            }
#pragma unroll
            for (int i = 0; i < 2; i++)
#pragma unroll
                for (int j = 0; j < 4; j++)
                    mma_tf32(c[i][j], a[i], b[j]);
        }
        __syncthreads();
    }

#pragma unroll
    for (int i = 0; i < 2; i++) {
        int r = row0 + warp * 32 + i * 16 + g;
#pragma unroll
        for (int j = 0; j < 4; j++) {
            int cc = col0 + j * 8 + 2 * t;
            float bx = 0.f, by = 0.f;
            if (bias) { bx = __ldg(bias + cc); by = __ldg(bias + cc + 1); }
            if (r < NN) {
                float2 o = make_float2(c[i][j][0] + bx, c[i][j][1] + by);
                *(float2*)(out + (size_t)r * OD + cc) = o;
            }
            if (r + 8 < NN) {
                float2 o = make_float2(c[i][j][2] + bx, c[i][j][3] + by);
                *(float2*)(out + (size_t)(r + 8) * OD + cc) = o;
            }
        }
    }

    if (ELR) {   // OD == 128: block covers exactly head h
#pragma unroll
        for (int i = 0; i < 2; i++) {
            float el0 = 0.f, el8 = 0.f, er0 = 0.f, er8 = 0.f;
#pragma unroll
            for (int j = 0; j < 4; j++) {
                int lc = j * 8 + 2 * t;
                float a0 = __ldg(al + h * 32 + lc), a1 = __ldg(al + h * 32 + lc + 1);
                float r0 = __ldg(ar + h * 32 + lc), r1 = __ldg(ar + h * 32 + lc + 1);
                el0 += c[i][j][0] * a0 + c[i][j][1] * a1;
                el8 += c[i][j][2] * a0 + c[i][j][3] * a1;
                er0 += c[i][j][0] * r0 + c[i][j][1] * r1;
                er8 += c[i][j][2] * r0 + c[i][j][3] * r1;
            }
#pragma unroll
            for (int o = 1; o <= 2; o <<= 1) {
                el0 += __shfl_xor_sync(0xffffffffu, el0, o);
                el8 += __shfl_xor_sync(0xffffffffu, el8, o);
                er0 += __shfl_xor_sync(0xffffffffu, er0, o);
                er8 += __shfl_xor_sync(0xffffffffu, er8, o);
            }
            if (t == 0) {
                int r = row0 + warp * 32 + i * 16 + g;
                if (r < NN)     { g_el[r * 4 + h] = el0;       g_er[r * 4 + h] = er0; }
                if (r + 8 < NN) { g_el[(r + 8) * 4 + h] = el8; g_er[(r + 8) * 4 + h] = er8; }
            }
        }
    }
}

// ---------------- el/er for layer 2 (F=40, heads not block-aligned) ----------------
__global__ void elr40_kernel(const float* __restrict__ al, const float* __restrict__ ar)
{
    int i = blockIdx.x * blockDim.x + threadIdx.x;
    if (i >= NN * 4) return;
    int h = i & 3;
    const float4* f  = (const float4*)(g_ft + (size_t)(i >> 2) * 160 + h * 40);
    const float4* A4 = (const float4*)(al + h * 40);
    const float4* B4 = (const float4*)(ar + h * 40);
    float a = 0.f, b = 0.f;
#pragma unroll
    for (int j = 0; j < 10; j++) {
        float4 v = f[j];
        float4 aa = __ldg(A4 + j);
        float4 bb = __ldg(B4 + j);
        a += v.x * aa.x + v.y * aa.y + v.z * aa.z + v.w * aa.w;
        b += v.x * bb.x + v.y * bb.y + v.z * bb.z + v.w * bb.w;
    }
    g_el[i] = a;
    g_er[i] = b;
}

// ================= fused per-dst softmax + aggregation (warp per node) =========
// MODE 0: rst = sk + msg, accumulate BN stats.  MODE 1: head-mean + log_softmax -> out.
template<int OD, int F, int MODE>
__global__ __launch_bounds__(256)
void gat_node_kernel(const float* __restrict__ bias_last, float* __restrict__ out)
{
    constexpr int NR = (OD / 4 + 31) / 32;
    __shared__ float s_sum[128], s_sq[128];
    __shared__ float s_row[8][160];

    const int tid = threadIdx.x;
    if (MODE == 0) {
        if (tid < 128) { s_sum[tid] = 0.f; s_sq[tid] = 0.f; }
        __syncthreads();
    }
    const int wn   = (blockIdx.x * 256 + tid) >> 5;
    const int lane = tid & 31;
    const int warp = tid >> 5;
    const bool active = wn < NN;

    float4 acc[NR];
    int headr[NR];
#pragma unroll
    for (int rp = 0; rp < NR; rp++) {
        acc[rp] = make_float4(0.f, 0.f, 0.f, 0.f);
        headr[rp] = ((lane + rp * 32) * 4) / F;
    }

    if (active) {
        const int beg = g_rowptr[wn], end = g_rowptr[wn + 1];
        const int deg = end - beg;
        const float4 er = *(const float4*)(g_er + (size_t)wn * 4);

        if (deg <= 32) {
            // ---- one gather pass, lane-local edge ----
            int sn = -1;
            float4 ev = make_float4(-FLT_MAX, -FLT_MAX, -FLT_MAX, -FLT_MAX);
            if (lane < deg) {
                sn = g_csr_src[beg + lane];
                float4 l = *(const float4*)(g_el + (size_t)sn * 4);
                ev.x = lrelu(l.x + er.x);
                ev.y = lrelu(l.y + er.y);
                ev.z = lrelu(l.z + er.z);
                ev.w = lrelu(l.w + er.w);
            }
            float4 m = ev;
#pragma unroll
            for (int o = 16; o; o >>= 1) {
                m.x = fmaxf(m.x, __shfl_xor_sync(0xffffffffu, m.x, o));
                m.y = fmaxf(m.y, __shfl_xor_sync(0xffffffffu, m.y, o));
                m.z = fmaxf(m.z, __shfl_xor_sync(0xffffffffu, m.z, o));
                m.w = fmaxf(m.w, __shfl_xor_sync(0xffffffffu, m.w, o));
            }
            float4 ex = make_float4(0.f, 0.f, 0.f, 0.f);
            if (lane < deg) {
                ex.x = __expf(ev.x - m.x);
                ex.y = __expf(ev.y - m.y);
                ex.z = __expf(ev.z - m.z);
                ex.w = __expf(ev.w - m.w);
            }
            float4 s = ex;
#pragma unroll
            for (int o = 16; o; o >>= 1) {
                s.x += __shfl_xor_sync(0xffffffffu, s.x, o);
                s.y += __shfl_xor_sync(0xffffffffu, s.y, o);
                s.z += __shfl_xor_sync(0xffffffffu, s.z, o);
                s.w += __shfl_xor_sync(0xffffffffu, s.w, o);
            }
            float4 av4 = make_float4(ex.x / s.x, ex.y / s.y, ex.z / s.z, ex.w / s.w);

            for (int i = 0; i < deg; i++) {
                int   si = __shfl_sync(0xffffffffu, sn, i);
                float ax = __shfl_sync(0xffffffffu, av4.x, i);
                float ay = __shfl_sync(0xffffffffu, av4.y, i);
                float az = __shfl_sync(0xffffffffu, av4.z, i);
                float aw = __shfl_sync(0xffffffffu, av4.w, i);
                const float* fp = g_ft + (size_t)si * OD;
#pragma unroll
                for (int rp = 0; rp < NR; rp++) {
                    int j4 = lane + rp * 32;
                    if (j4 < OD / 4) {
                        int hh = headr[rp];
                        float a = (hh == 0) ? ax : (hh == 1) ? ay : (hh == 2) ? az : aw;
                        float4 f = *(const float4*)(fp + j4 * 4);
                        acc[rp].x += a * f.x;
                        acc[rp].y += a * f.y;
                        acc[rp].z += a * f.z;
                        acc[rp].w += a * f.w;
                    }
                }
            }
        } else {
            // ---- rare high-degree fallback: 3-phase with staging ----
            float4 m = make_float4(-FLT_MAX, -FLT_MAX, -FLT_MAX, -FLT_MAX);
            for (int i = beg + lane; i < end; i += 32) {
                int sn = g_csr_src[i];
                float4 l = *(const float4*)(g_el + (size_t)sn * 4);
                m.x = fmaxf(m.x, lrelu(l.x + er.x));
                m.y = fmaxf(m.y, lrelu(l.y + er.y));
                m.z = fmaxf(m.z, lrelu(l.z + er.z));
                m.w = fmaxf(m.w, lrelu(l.w + er.w));
            }
#pragma unroll
            for (int o = 16; o; o >>= 1) {
                m.x = fmaxf(m.x, __shfl_xor_sync(0xffffffffu, m.x, o));
                m.y = fmaxf(m.y, __shfl_xor_sync(0xffffffffu, m.y, o));
                m.z = fmaxf(m.z, __shfl_xor_sync(0xffffffffu, m.z, o));
                m.w = fmaxf(m.w, __shfl_xor_sync(0xffffffffu, m.w, o));
            }
            float4 s = make_float4(0.f, 0.f, 0.f, 0.f);
            for (int i = beg + lane; i < end; i += 32) {
                int sn = g_csr_src[i];
                float4 l = *(const float4*)(g_el + (size_t)sn * 4);
                float4 ex;
                ex.x = __expf(lrelu(l.x + er.x) - m.x);
                ex.y = __expf(lrelu(l.y + er.y) - m.y);
                ex.z = __expf(lrelu(l.z + er.z) - m.z);
                ex.w = __expf(lrelu(l.w + er.w) - m.w);
                *(float4*)(g_ex + (size_t)i * 4) = ex;
                s.x += ex.x; s.y += ex.y; s.z += ex.z; s.w += ex.w;
            }
#pragma unroll
            for (int o = 16; o; o >>= 1) {
                s.x += __shfl_xor_sync(0xffffffffu, s.x, o);
                s.y += __shfl_xor_sync(0xffffffffu, s.y, o);
                s.z += __shfl_xor_sync(0xffffffffu, s.z, o);
                s.w += __shfl_xor_sync(0xffffffffu, s.w, o);
            }
            float4 inv = make_float4(1.f / s.x, 1.f / s.y, 1.f / s.z, 1.f / s.w);
            float invh[NR];
#pragma unroll
            for (int rp = 0; rp < NR; rp++) {
                int hh = headr[rp];
                invh[rp] = (hh == 0) ? inv.x : (hh == 1) ? inv.y : (hh == 2) ? inv.z : inv.w;
            }
            for (int i = beg; i < end; i++) {
                int sn = g_csr_src[i];
                float4 exv = *(const float4*)(g_ex + (size_t)i * 4);
                const float* fp = g_ft + (size_t)sn * OD;
#pragma unroll
                for (int rp = 0; rp < NR; rp++) {
                    int j4 = lane + rp * 32;
                    if (j4 < OD / 4) {
                        int hh = headr[rp];
                        float a = ((hh == 0) ? exv.x : (hh == 1) ? exv.y :
                                   (hh == 2) ? exv.z : exv.w) * invh[rp];
                        float4 f = *(const float4*)(fp + j4 * 4);
                        acc[rp].x += a * f.x;
                        acc[rp].y += a * f.y;
                        acc[rp].z += a * f.z;
                        acc[rp].w += a * f.w;
                    }
                }
            }
        }
    }

    if (MODE == 0) {
        if (active) {
            const float* skp = g_sk  + (size_t)wn * OD;
            float*       rp_ = g_rst + (size_t)wn * OD;
#pragma unroll
            for (int rp = 0; rp < NR; rp++) {
                int j4 = lane + rp * 32;
                if (j4 < OD / 4) {
                    float4 sk = *(const float4*)(skp + j4 * 4);
                    float4 r;
                    r.x = sk.x + acc[rp].x; r.y = sk.y + acc[rp].y;
                    r.z = sk.z + acc[rp].z; r.w = sk.w + acc[rp].w;
                    *(float4*)(rp_ + j4 * 4) = r;
                    int c0 = j4 * 4;
                    atomicAdd(&s_sum[c0 + 0], r.x); atomicAdd(&s_sq[c0 + 0], r.x * r.x);
                    atomicAdd(&s_sum[c0 + 1], r.y); atomicAdd(&s_sq[c0 + 1], r.y * r.y);
                    atomicAdd(&s_sum[c0 + 2], r.z); atomicAdd(&s_sq[c0 + 2], r.z * r.z);
                    atomicAdd(&s_sum[c0 + 3], r.w); atomicAdd(&s_sq[c0 + 3], r.w * r.w);
                }
            }
        }
        __syncthreads();
        if (tid < 128) {
            atomicAdd(&g_bnsum[tid], s_sum[tid]);
            atomicAdd(&g_bnsq[tid],  s_sq[tid]);
        }
    } else {
        if (active) {
            const float* skp = g_sk + (size_t)wn * OD;
#pragma unroll
            for (int rp = 0; rp < NR; rp++) {
                int j4 = lane + rp * 32;
                if (j4 < OD / 4) {
                    float4 sk = *(const float4*)(skp + j4 * 4);
                    float* d = &s_row[warp][j4 * 4];
                    d[0] = sk.x + acc[rp].x;
                    d[1] = sk.y + acc[rp].y;
                    d[2] = sk.z + acc[rp].z;
                    d[3] = sk.w + acc[rp].w;
                }
            }
            __syncwarp();
            const float* r = s_row[warp];
            float v0 = 0.25f * (r[lane] + r[40 + lane] + r[80 + lane] + r[120 + lane])
                     + __ldg(bias_last + lane);
            float v1 = -FLT_MAX;
            if (lane < 8) {
                int c1 = lane + 32;
                v1 = 0.25f * (r[c1] + r[40 + c1] + r[80 + c1] + r[120 + c1])
                   + __ldg(bias_last + c1);
            }
            float mx = fmaxf(v0, v1);
#pragma unroll
            for (int o = 16; o; o >>= 1) mx = fmaxf(mx, __shfl_xor_sync(0xffffffffu, mx, o));
            float se = __expf(v0 - mx) + (lane < 8 ? __expf(v1 - mx) : 0.f);
#pragma unroll
            for (int o = 16; o; o >>= 1) se += __shfl_xor_sync(0xffffffffu, se, o);
            float lse = logf(se);
            out[(size_t)wn * 40 + lane] = v0 - mx - lse;
            if (lane < 8) out[(size_t)wn * 40 + lane + 32] = v1 - mx - lse;
        }
    }
}

// ---------------- BN finalize: fold stats into per-column scale/shift ----------------
__global__ void bn_finalize_kernel(const float* __restrict__ gam, const float* __restrict__ be)
{
    int c = threadIdx.x;   // 128
    const float invN = 1.f / (float)NN;
    float mean = g_bnsum[c] * invN;
    float var  = g_bnsq[c] * invN - mean * mean;
    float a = __ldg(gam + c) * rsqrtf(var + 1e-5f);
    g_bna[c] = a;
    g_bnb[c] = __ldg(be + c) - mean * a;
    g_bnsum[c] = 0.f;
    g_bnsq[c]  = 0.f;
}

// ---------------- launch ----------------
extern "C" void kernel_launch(void* const* d_in, const int* in_sizes, int n_in,
                              void* d_out, int out_size)
{
    (void)in_sizes; (void)n_in; (void)out_size;
    const float* feat   = (const float*)d_in[0];
    const int*   src    = (const int*)  d_in[1];
    const int*   dst    = (const int*)  d_in[2];
    const float* w_fc0  = (const float*)d_in[3];
    const float* al0    = (const float*)d_in[4];
    const float* ar0    = (const float*)d_in[5];
    const float* b0     = (const float*)d_in[6];
    const float* w_lin0 = (const float*)d_in[7];
    const float* gam0   = (const float*)d_in[8];
    const float* be0    = (const float*)d_in[9];
    const float* w_fc1  = (const float*)d_in[10];
    const float* al1    = (const float*)d_in[11];
    const float* ar1    = (const float*)d_in[12];
    const float* b1     = (const float*)d_in[13];
    const float* w_lin1 = (const float*)d_in[14];
    const float* gam1   = (const float*)d_in[15];
    const float* be1    = (const float*)d_in[16];
    const float* w_fc2  = (const float*)d_in[17];
    const float* al2    = (const float*)d_in[18];
    const float* ar2    = (const float*)d_in[19];
    const float* b2     = (const float*)d_in[20];
    const float* w_lin2 = (const float*)d_in[21];
    const float* blast  = (const float*)d_in[22];

    float *ft, *rst, *sk;
    cudaGetSymbolAddress((void**)&ft,  g_ft);
    cudaGetSymbolAddress((void**)&rst, g_rst);
    cudaGetSymbolAddress((void**)&sk,  g_sk);

    const dim3 g128((NN + 127) / 128, 4);
    const dim3 g160((NN + 127) / 128, 5);
    const int EB   = (EE + 255) / 256;
    const int NB   = (NN + 255) / 256;
    const int NODB = (NN * 32 + 255) / 256;   // warp per node
    const int NHB  = (NN * 4 + 255) / 256;

    // ---- CSR build + BN-accumulator zero ----
    zero_all_kernel<<<NB, 256>>>();
    hist_kernel<<<EB, 256>>>(dst);
    scan1_kernel<<<NSCAN, 1024>>>();
    scan2_kernel<<<1, 64>>>();
    scan3_kernel<<<NSCAN, 1024>>>();
    scatter_kernel<<<EB, 256>>>(src, dst);

    // ---- layer 0 ----
    gemm_tc<128, false, true ><<<g128, 128>>>(feat, w_fc0,  nullptr, ft, al0, ar0);
    gemm_tc<128, false, false><<<g128, 128>>>(feat, w_lin0, b0,      sk, nullptr, nullptr);
    gat_node_kernel<128, 32, 0><<<NODB, 256>>>(nullptr, nullptr);
    bn_finalize_kernel<<<1, 128>>>(gam0, be0);

    // ---- layer 1 (BN+ReLU fused into A-tile load) ----
    gemm_tc<128, true, true ><<<g128, 128>>>(rst, w_fc1,  nullptr, ft, al1, ar1);
    gemm_tc<128, true, false><<<g128, 128>>>(rst, w_lin1, b1,      sk, nullptr, nullptr);
    gat_node_kernel<128, 32, 0><<<NODB, 256>>>(nullptr, nullptr);
    bn_finalize_kernel<<<1, 128>>>(gam1, be1);

    // ---- layer 2 + fused final ----
    gemm_tc<160, true, false><<<g160, 128>>>(rst, w_fc2,  nullptr, ft, nullptr, nullptr);
    elr40_kernel<<<NHB, 256>>>(al2, ar2);
    gemm_tc<160, true, false><<<g160, 128>>>(rst, w_lin2, b2,      sk, nullptr, nullptr);
    gat_node_kernel<160, 40, 1><<<NODB, 256>>>(blast, (float*)d_out);
}

// round 11
// speedup vs baseline: 2.1797x; 1.1909x over previous
#include <cuda_runtime.h>
#include <math.h>
#include <float.h>

#define NN 50000
#define EE 800000

// ---------------- persistent scratch (device globals; no allocation) ----------------
__device__ float g_ft [NN * 160];   // transformed features [N, H*F]
__device__ float g_rst[NN * 160];   // layer output (post message-passing)
__device__ float g_sk [NN * 160];   // skip + bias buffer
__device__ float g_el [NN * 4];
__device__ float g_er [NN * 4];
__device__ float g_ex [EE * 4];     // staging for rare high-degree nodes
__device__ int   g_rowptr[NN + 1];
__device__ int   g_tmp   [NN];
__device__ int   g_csr_src[EE];
__device__ float g_bnsum[2][128], g_bnsq[2][128];   // ping-pong BN stats

__device__ __forceinline__ float lrelu(float x) { return x > 0.f ? x : 0.2f * x; }

__device__ __forceinline__ float tf32r(float x) {
    unsigned u;
    asm("cvt.rna.tf32.f32 %0, %1;" : "=r"(u) : "f"(x));
    return __uint_as_float(u);
}

__device__ __forceinline__ void mma_tf32(float* c, const unsigned* a, const unsigned* b) {
    asm volatile(
        "mma.sync.aligned.m16n8k8.row.col.f32.tf32.tf32.f32 "
        "{%0,%1,%2,%3}, {%4,%5,%6,%7}, {%8,%9}, {%0,%1,%2,%3};\n"
        : "+f"(c[0]), "+f"(c[1]), "+f"(c[2]), "+f"(c[3])
        : "r"(a[0]), "r"(a[1]), "r"(a[2]), "r"(a[3]), "r"(b[0]), "r"(b[1]));
}

// ================= CSR build =================
__global__ void zero_all_kernel()
{
    int i = blockIdx.x * blockDim.x + threadIdx.x;
    if (i < NN)  g_tmp[i] = 0;
    if (i < 128) {
        g_bnsum[0][i] = 0.f; g_bnsq[0][i] = 0.f;
        g_bnsum[1][i] = 0.f; g_bnsq[1][i] = 0.f;
    }
}

__global__ void hist_kernel(const int* __restrict__ dst)
{
    int e = blockIdx.x * blockDim.x + threadIdx.x;
    if (e < EE) atomicAdd(&g_tmp[dst[e]], 1);
}

// one-block scan of all NN counts in dynamic smem -> g_rowptr & g_tmp
extern __shared__ int s_scan[];
__global__ __launch_bounds__(1024) void scan_all_kernel()
{
    __shared__ int wsum[32];
    const int t = threadIdx.x, lane = t & 31, wid = t >> 5;
    for (int i = t; i < NN; i += 1024) s_scan[i] = g_tmp[i];
    __syncthreads();

    const int C = (NN + 1023) / 1024;      // 49
    const int base = t * C;
    int sum = 0;
#pragma unroll 7
    for (int i = 0; i < C; i++) {
        int idx = base + i;
        if (idx < NN) sum += s_scan[idx];
    }
    int x = sum;
#pragma unroll
    for (int o = 1; o < 32; o <<= 1) {
        int y = __shfl_up_sync(0xffffffffu, x, o);
        if (lane >= o) x += y;
    }
    if (lane == 31) wsum[wid] = x;
    __syncthreads();
    if (wid == 0) {
        int w = wsum[lane];
#pragma unroll
        for (int o = 1; o < 32; o <<= 1) {
            int y = __shfl_up_sync(0xffffffffu, w, o);
            if (lane >= o) w += y;
        }
        wsum[lane] = w;
    }
    __syncthreads();
    int run = (x - sum) + (wid ? wsum[wid - 1] : 0);
#pragma unroll 7
    for (int i = 0; i < C; i++) {
        int idx = base + i;
        if (idx < NN) { int v = s_scan[idx]; s_scan[idx] = run; run += v; }
    }
    __syncthreads();
    for (int i = t; i < NN; i += 1024) {
        int v = s_scan[i];
        g_rowptr[i] = v;
        g_tmp[i]    = v;
    }
    if (t == 0) g_rowptr[NN] = EE;
}

__global__ void scatter_kernel(const int* __restrict__ src, const int* __restrict__ dst)
{
    int e = blockIdx.x * blockDim.x + threadIdx.x;
    if (e >= EE) return;
    int pos = atomicAdd(&g_tmp[dst[e]], 1);
    g_csr_src[pos] = src[e];
}

// ---------------- merged tf32 GEMM: one launch does fc AND lin ----------------
// blockIdx.y < OD/32 -> fc (out=ft, optional fused el/er); else lin (out=sk, +bias)
// BN: x <- relu(a*x+b) on A-tile load; scale/shift computed in-block from raw stats.
template<int OD, bool BN>
__global__ __launch_bounds__(128)
void gemm_tc(const float* __restrict__ X,
             const float* __restrict__ Wfc, const float* __restrict__ Wlin,
             const float* __restrict__ bias, float* __restrict__ ft_out,
             float* __restrict__ sk_out,
             const float* __restrict__ al, const float* __restrict__ ar,
             const float* __restrict__ gam, const float* __restrict__ be, int sel)
{
    constexpr int NCB = OD / 32;
    __shared__ float As[128 * 37];
    __shared__ float Bs[32 * 37];
    __shared__ float s_a[128], s_b[128];
    const int tid  = threadIdx.x;
    const int warp = tid >> 5, lane = tid & 31;
    const int g    = lane >> 2, t = lane & 3;
    const int row0 = blockIdx.x * 128;
    const bool isFC = blockIdx.y < NCB;
    const int cb   = isFC ? blockIdx.y : blockIdx.y - NCB;
    const int col0 = cb * 32;
    const float* __restrict__ W = isFC ? Wfc : Wlin;
    float* __restrict__ out     = isFC ? ft_out : sk_out;

    if (BN) {
        if (tid < 128) {
            float sum = g_bnsum[sel][tid], sq = g_bnsq[sel][tid];
            const float invN = 1.f / (float)NN;
            float mean = sum * invN;
            float var  = sq * invN - mean * mean;
            float a = __ldg(gam + tid) * rsqrtf(var + 1e-5f);
            s_a[tid] = a;
            s_b[tid] = __ldg(be + tid) - mean * a;
        }
        __syncthreads();
    }

    float c[2][4][4];
#pragma unroll
    for (int i = 0; i < 2; i++)
#pragma unroll
        for (int j = 0; j < 4; j++)
#pragma unroll
            for (int q = 0; q < 4; q++) c[i][j][q] = 0.f;

#pragma unroll
    for (int kb = 0; kb < 128; kb += 32) {
#pragma unroll
        for (int j = 0; j < 8; j++) {
            int i4 = tid + j * 128;
            int r  = i4 >> 3;
            int k4 = (i4 & 7) << 2;
            float4 v = make_float4(0.f, 0.f, 0.f, 0.f);
            if (row0 + r < NN)
                v = *(const float4*)(X + (size_t)(row0 + r) * 128 + kb + k4);
            if (BN) {
                v.x = fmaxf(s_a[kb + k4 + 0] * v.x + s_b[kb + k4 + 0], 0.f);
                v.y = fmaxf(s_a[kb + k4 + 1] * v.y + s_b[kb + k4 + 1], 0.f);
                v.z = fmaxf(s_a[kb + k4 + 2] * v.z + s_b[kb + k4 + 2], 0.f);
                v.w = fmaxf(s_a[kb + k4 + 3] * v.w + s_b[kb + k4 + 3], 0.f);
            }
            float* ap = &As[r * 37 + k4];
            ap[0] = tf32r(v.x); ap[1] = tf32r(v.y); ap[2] = tf32r(v.z); ap[3] = tf32r(v.w);
        }
#pragma unroll
        for (int j = 0; j < 2; j++) {
            int i4 = tid + j * 128;
            int k  = i4 >> 3;
            int n4 = (i4 & 7) << 2;
            float4 v = *(const float4*)(W + (size_t)(kb + k) * OD + col0 + n4);
            Bs[(n4 + 0) * 37 + k] = tf32r(v.x);
            Bs[(n4 + 1) * 37 + k] = tf32r(v.y);
            Bs[(n4 + 2) * 37 + k] = tf32r(v.z);
            Bs[(n4 + 3) * 37 + k] = tf32r(v.w);
        }
        __syncthreads();
#pragma unroll
        for (int ks = 0; ks < 4; ks++) {
            const int k0 = ks * 8;
            unsigned a[2][4], b[4][2];
            const int mbase = warp * 32;
#pragma unroll
            for (int i = 0; i < 2; i++) {
                const float* ap = As + (mbase + i * 16 + g) * 37 + k0 + t;
                a[i][0] = __float_as_uint(ap[0]);
                a[i][1] = __float_as_uint(ap[8 * 37]);
                a[i][2] = __float_as_uint(ap[4]);
                a[i][3] = __float_as_uint(ap[8 * 37 + 4]);
            }
#pragma unroll
            for (int j = 0; j < 4; j++) {
                const float* bp = Bs + (j * 8 + g) * 37 + k0 + t;
                b[j][0] = __float_as_uint(bp[0]);
                b[j][1] = __float_as_uint(bp[4]);
            }
#pragma unroll
            for (int i = 0; i < 2; i++)
#pragma unroll
                for (int j = 0; j < 4; j++)
                    mma_tf32(c[i][j], a[i], b[j]);
        }
        __syncthreads();
    }

#pragma unroll
    for (int i = 0; i < 2; i++) {
        int r = row0 + warp * 32 + i * 16 + g;
#pragma unroll
        for (int j = 0; j < 4; j++) {
            int cc = col0 + j * 8 + 2 * t;
            float bx = 0.f, by = 0.f;
            if (!isFC) { bx = __ldg(bias + cc); by = __ldg(bias + cc + 1); }
            if (r < NN) {
                float2 o = make_float2(c[i][j][0] + bx, c[i][j][1] + by);
                *(float2*)(out + (size_t)r * OD + cc) = o;
            }
            if (r + 8 < NN) {
                float2 o = make_float2(c[i][j][2] + bx, c[i][j][3] + by);
                *(float2*)(out + (size_t)(r + 8) * OD + cc) = o;
            }
        }
    }

    if (OD == 128 && isFC && al != nullptr) {   // fused el/er: col block == head cb
        const int h = cb;
#pragma unroll
        for (int i = 0; i < 2; i++) {
            float el0 = 0.f, el8 = 0.f, er0 = 0.f, er8 = 0.f;
#pragma unroll
            for (int j = 0; j < 4; j++) {
                int lc = j * 8 + 2 * t;
                float a0 = __ldg(al + h * 32 + lc), a1 = __ldg(al + h * 32 + lc + 1);
                float r0 = __ldg(ar + h * 32 + lc), r1 = __ldg(ar + h * 32 + lc + 1);
                el0 += c[i][j][0] * a0 + c[i][j][1] * a1;
                el8 += c[i][j][2] * a0 + c[i][j][3] * a1;
                er0 += c[i][j][0] * r0 + c[i][j][1] * r1;
                er8 += c[i][j][2] * r0 + c[i][j][3] * r1;
            }
#pragma unroll
            for (int o = 1; o <= 2; o <<= 1) {
                el0 += __shfl_xor_sync(0xffffffffu, el0, o);
                el8 += __shfl_xor_sync(0xffffffffu, el8, o);
                er0 += __shfl_xor_sync(0xffffffffu, er0, o);
                er8 += __shfl_xor_sync(0xffffffffu, er8, o);
            }
            if (t == 0) {
                int r = row0 + warp * 32 + i * 16 + g;
                if (r < NN)     { g_el[r * 4 + h] = el0;       g_er[r * 4 + h] = er0; }
                if (r + 8 < NN) { g_el[(r + 8) * 4 + h] = el8; g_er[(r + 8) * 4 + h] = er8; }
            }
        }
    }
}

// ---------------- el/er for layer 2 (F=40, heads not block-aligned) ----------------
__global__ void elr40_kernel(const float* __restrict__ al, const float* __restrict__ ar)
{
    int i = blockIdx.x * blockDim.x + threadIdx.x;
    if (i >= NN * 4) return;
    int h = i & 3;
    const float4* f  = (const float4*)(g_ft + (size_t)(i >> 2) * 160 + h * 40);
    const float4* A4 = (const float4*)(al + h * 40);
    const float4* B4 = (const float4*)(ar + h * 40);
    float a = 0.f, b = 0.f;
#pragma unroll
    for (int j = 0; j < 10; j++) {
        float4 v = f[j];
        float4 aa = __ldg(A4 + j);
        float4 bb = __ldg(B4 + j);
        a += v.x * aa.x + v.y * aa.y + v.z * aa.z + v.w * aa.w;
        b += v.x * bb.x + v.y * bb.y + v.z * bb.z + v.w * bb.w;
    }
    g_el[i] = a;
    g_er[i] = b;
}

// ================= fused per-dst softmax + aggregation (warp per node) =========
// MODE 0: rst = sk + msg, accumulate BN stats into buffer [sel].
// MODE 1: head-mean + log_softmax -> out.
template<int OD, int F, int MODE>
__global__ __launch_bounds__(256)
void gat_node_kernel(const float* __restrict__ bias_last, float* __restrict__ out, int sel)
{
    constexpr int NR = (OD / 4 + 31) / 32;
    __shared__ float s_sum[128], s_sq[128];
    __shared__ float s_row[8][160];
    __shared__ int   s_sn [8][32];
    __shared__ float s_att[8][32][4];

    const int tid = threadIdx.x;
    if (MODE == 0) {
        if (tid < 128) { s_sum[tid] = 0.f; s_sq[tid] = 0.f; }
        __syncthreads();
    }
    const int wn   = (blockIdx.x * 256 + tid) >> 5;
    const int lane = tid & 31;
    const int warp = tid >> 5;
    const bool active = wn < NN;

    float4 acc[NR];
    int headr[NR];
#pragma unroll
    for (int rp = 0; rp < NR; rp++) {
        acc[rp] = make_float4(0.f, 0.f, 0.f, 0.f);
        headr[rp] = ((lane + rp * 32) * 4) / F;
    }

    if (active) {
        const int beg = g_rowptr[wn], end = g_rowptr[wn + 1];
        const int deg = end - beg;
        const float4 er = *(const float4*)(g_er + (size_t)wn * 4);

        if (deg <= 32) {
            // ---- one gather pass, lane-local edge ----
            int sn = -1;
            float4 ev = make_float4(-FLT_MAX, -FLT_MAX, -FLT_MAX, -FLT_MAX);
            if (lane < deg) {
                sn = g_csr_src[beg + lane];
                float4 l = *(const float4*)(g_el + (size_t)sn * 4);
                ev.x = lrelu(l.x + er.x);
                ev.y = lrelu(l.y + er.y);
                ev.z = lrelu(l.z + er.z);
                ev.w = lrelu(l.w + er.w);
            }
            float4 m = ev;
#pragma unroll
            for (int o = 16; o; o >>= 1) {
                m.x = fmaxf(m.x, __shfl_xor_sync(0xffffffffu, m.x, o));
                m.y = fmaxf(m.y, __shfl_xor_sync(0xffffffffu, m.y, o));
                m.z = fmaxf(m.z, __shfl_xor_sync(0xffffffffu, m.z, o));
                m.w = fmaxf(m.w, __shfl_xor_sync(0xffffffffu, m.w, o));
            }
            float4 ex = make_float4(0.f, 0.f, 0.f, 0.f);
            if (lane < deg) {
                ex.x = __expf(ev.x - m.x);
                ex.y = __expf(ev.y - m.y);
                ex.z = __expf(ev.z - m.z);
                ex.w = __expf(ev.w - m.w);
            }
            float4 s = ex;
#pragma unroll
            for (int o = 16; o; o >>= 1) {
                s.x += __shfl_xor_sync(0xffffffffu, s.x, o);
                s.y += __shfl_xor_sync(0xffffffffu, s.y, o);
                s.z += __shfl_xor_sync(0xffffffffu, s.z, o);
                s.w += __shfl_xor_sync(0xffffffffu, s.w, o);
            }
            // stash per-edge src + attention in smem (kills 5 shfls/edge below)
            s_sn[warp][lane] = sn;
            s_att[warp][lane][0] = ex.x / s.x;
            s_att[warp][lane][1] = ex.y / s.y;
            s_att[warp][lane][2] = ex.z / s.z;
            s_att[warp][lane][3] = ex.w / s.w;
            __syncwarp();

            for (int i = 0; i < deg; i++) {
                int si = s_sn[warp][i];
                const float* fp = g_ft + (size_t)si * OD;
#pragma unroll
                for (int rp = 0; rp < NR; rp++) {
                    int j4 = lane + rp * 32;
                    if (j4 < OD / 4) {
                        float a = s_att[warp][i][headr[rp]];
                        float4 f = *(const float4*)(fp + j4 * 4);
                        acc[rp].x += a * f.x;
                        acc[rp].y += a * f.y;
                        acc[rp].z += a * f.z;
                        acc[rp].w += a * f.w;
                    }
                }
            }
        } else {
            // ---- rare high-degree fallback: 3-phase with staging ----
            float4 m = make_float4(-FLT_MAX, -FLT_MAX, -FLT_MAX, -FLT_MAX);
            for (int i = beg + lane; i < end; i += 32) {
                int sn = g_csr_src[i];
                float4 l = *(const float4*)(g_el + (size_t)sn * 4);
                m.x = fmaxf(m.x, lrelu(l.x + er.x));
                m.y = fmaxf(m.y, lrelu(l.y + er.y));
                m.z = fmaxf(m.z, lrelu(l.z + er.z));
                m.w = fmaxf(m.w, lrelu(l.w + er.w));
            }
#pragma unroll
            for (int o = 16; o; o >>= 1) {
                m.x = fmaxf(m.x, __shfl_xor_sync(0xffffffffu, m.x, o));
                m.y = fmaxf(m.y, __shfl_xor_sync(0xffffffffu, m.y, o));
                m.z = fmaxf(m.z, __shfl_xor_sync(0xffffffffu, m.z, o));
                m.w = fmaxf(m.w, __shfl_xor_sync(0xffffffffu, m.w, o));
            }
            float4 s = make_float4(0.f, 0.f, 0.f, 0.f);
            for (int i = beg + lane; i < end; i += 32) {
                int sn = g_csr_src[i];
                float4 l = *(const float4*)(g_el + (size_t)sn * 4);
                float4 ex;
                ex.x = __expf(lrelu(l.x + er.x) - m.x);
                ex.y = __expf(lrelu(l.y + er.y) - m.y);
                ex.z = __expf(lrelu(l.z + er.z) - m.z);
                ex.w = __expf(lrelu(l.w + er.w) - m.w);
                *(float4*)(g_ex + (size_t)i * 4) = ex;
                s.x += ex.x; s.y += ex.y; s.z += ex.z; s.w += ex.w;
            }
#pragma unroll
            for (int o = 16; o; o >>= 1) {
                s.x += __shfl_xor_sync(0xffffffffu, s.x, o);
                s.y += __shfl_xor_sync(0xffffffffu, s.y, o);
                s.z += __shfl_xor_sync(0xffffffffu, s.z, o);
                s.w += __shfl_xor_sync(0xffffffffu, s.w, o);
            }
            float4 inv = make_float4(1.f / s.x, 1.f / s.y, 1.f / s.z, 1.f / s.w);
            float invh[NR];
#pragma unroll
            for (int rp = 0; rp < NR; rp++) {
                int hh = headr[rp];
                invh[rp] = (hh == 0) ? inv.x : (hh == 1) ? inv.y : (hh == 2) ? inv.z : inv.w;
            }
            for (int i = beg; i < end; i++) {
                int sn = g_csr_src[i];
                float4 exv = *(const float4*)(g_ex + (size_t)i * 4);
                const float* fp = g_ft + (size_t)sn * OD;
#pragma unroll
                for (int rp = 0; rp < NR; rp++) {
                    int j4 = lane + rp * 32;
                    if (j4 < OD / 4) {
                        int hh = headr[rp];
                        float a = ((hh == 0) ? exv.x : (hh == 1) ? exv.y :
                                   (hh == 2) ? exv.z : exv.w) * invh[rp];
                        float4 f = *(const float4*)(fp + j4 * 4);
                        acc[rp].x += a * f.x;
                        acc[rp].y += a * f.y;
                        acc[rp].z += a * f.z;
                        acc[rp].w += a * f.w;
                    }
                }
            }
        }
    }

    if (MODE == 0) {
        if (active) {
            const float* skp = g_sk  + (size_t)wn * OD;
            float*       rp_ = g_rst + (size_t)wn * OD;
#pragma unroll
            for (int rp = 0; rp < NR; rp++) {
                int j4 = lane + rp * 32;
                if (j4 < OD / 4) {
                    float4 sk = *(const float4*)(skp + j4 * 4);
                    float4 r;
                    r.x = sk.x + acc[rp].x; r.y = sk.y + acc[rp].y;
                    r.z = sk.z + acc[rp].z; r.w = sk.w + acc[rp].w;
                    *(float4*)(rp_ + j4 * 4) = r;
                    int c0 = j4 * 4;
                    atomicAdd(&s_sum[c0 + 0], r.x); atomicAdd(&s_sq[c0 + 0], r.x * r.x);
                    atomicAdd(&s_sum[c0 + 1], r.y); atomicAdd(&s_sq[c0 + 1], r.y * r.y);
                    atomicAdd(&s_sum[c0 + 2], r.z); atomicAdd(&s_sq[c0 + 2], r.z * r.z);
                    atomicAdd(&s_sum[c0 + 3], r.w); atomicAdd(&s_sq[c0 + 3], r.w * r.w);
                }
            }
        }
        __syncthreads();
        if (tid < 128) {
            atomicAdd(&g_bnsum[sel][tid], s_sum[tid]);
            atomicAdd(&g_bnsq[sel][tid],  s_sq[tid]);
        }
    } else {
        if (active) {
            const float* skp = g_sk + (size_t)wn * OD;
#pragma unroll
            for (int rp = 0; rp < NR; rp++) {
                int j4 = lane + rp * 32;
                if (j4 < OD / 4) {
                    float4 sk = *(const float4*)(skp + j4 * 4);
                    float* d = &s_row[warp][j4 * 4];
                    d[0] = sk.x + acc[rp].x;
                    d[1] = sk.y + acc[rp].y;
                    d[2] = sk.z + acc[rp].z;
                    d[3] = sk.w + acc[rp].w;
                }
            }
            __syncwarp();
            const float* r = s_row[warp];
            float v0 = 0.25f * (r[lane] + r[40 + lane] + r[80 + lane] + r[120 + lane])
                     + __ldg(bias_last + lane);
            float v1 = -FLT_MAX;
            if (lane < 8) {
                int c1 = lane + 32;
                v1 = 0.25f * (r[c1] + r[40 + c1] + r[80 + c1] + r[120 + c1])
                   + __ldg(bias_last + c1);
            }
            float mx = fmaxf(v0, v1);
#pragma unroll
            for (int o = 16; o; o >>= 1) mx = fmaxf(mx, __shfl_xor_sync(0xffffffffu, mx, o));
            float se = __expf(v0 - mx) + (lane < 8 ? __expf(v1 - mx) : 0.f);
#pragma unroll
            for (int o = 16; o; o >>= 1) se += __shfl_xor_sync(0xffffffffu, se, o);
            float lse = logf(se);
            out[(size_t)wn * 40 + lane] = v0 - mx - lse;
            if (lane < 8) out[(size_t)wn * 40 + lane + 32] = v1 - mx - lse;
        }
    }
}

// ---------------- launch ----------------
extern "C" void kernel_launch(void* const* d_in, const int* in_sizes, int n_in,
                              void* d_out, int out_size)
{
    (void)in_sizes; (void)n_in; (void)out_size;
    const float* feat   = (const float*)d_in[0];
    const int*   src    = (const int*)  d_in[1];
    const int*   dst    = (const int*)  d_in[2];
    const float* w_fc0  = (const float*)d_in[3];
    const float* al0    = (const float*)d_in[4];
    const float* ar0    = (const float*)d_in[5];
    const float* b0     = (const float*)d_in[6];
    const float* w_lin0 = (const float*)d_in[7];
    const float* gam0   = (const float*)d_in[8];
    const float* be0    = (const float*)d_in[9];
    const float* w_fc1  = (const float*)d_in[10];
    const float* al1    = (const float*)d_in[11];
    const float* ar1    = (const float*)d_in[12];
    const float* b1     = (const float*)d_in[13];
    const float* w_lin1 = (const float*)d_in[14];
    const float* gam1   = (const float*)d_in[15];
    const float* be1    = (const float*)d_in[16];
    const float* w_fc2  = (const float*)d_in[17];
    const float* al2    = (const float*)d_in[18];
    const float* ar2    = (const float*)d_in[19];
    const float* b2     = (const float*)d_in[20];
    const float* w_lin2 = (const float*)d_in[21];
    const float* blast  = (const float*)d_in[22];

    float *ft, *rst, *sk;
    cudaGetSymbolAddress((void**)&ft,  g_ft);
    cudaGetSymbolAddress((void**)&rst, g_rst);
    cudaGetSymbolAddress((void**)&sk,  g_sk);

    static bool attr_done = false;
    if (!attr_done) {
        cudaFuncSetAttribute(scan_all_kernel,
                             cudaFuncAttributeMaxDynamicSharedMemorySize, NN * 4);
        attr_done = true;
    }

    const dim3 g128((NN + 127) / 128, 8);    // 4 fc + 4 lin col-blocks
    const dim3 g160((NN + 127) / 128, 10);   // 5 fc + 5 lin col-blocks
    const int EB   = (EE + 255) / 256;
    const int NB   = (NN + 255) / 256;
    const int NODB = (NN * 32 + 255) / 256;  // warp per node
    const int NHB  = (NN * 4 + 255) / 256;

    // ---- CSR build + BN-accumulator zero ----
    zero_all_kernel<<<NB, 256>>>();
    hist_kernel<<<EB, 256>>>(dst);
    scan_all_kernel<<<1, 1024, NN * 4>>>();
    scatter_kernel<<<EB, 256>>>(src, dst);

    // ---- layer 0 ----
    gemm_tc<128, false><<<g128, 128>>>(feat, w_fc0, w_lin0, b0, ft, sk,
                                       al0, ar0, nullptr, nullptr, 0);
    gat_node_kernel<128, 32, 0><<<NODB, 256>>>(nullptr, nullptr, 0);

    // ---- layer 1 (BN+ReLU fused into A-tile load, stats from buffer 0) ----
    gemm_tc<128, true><<<g128, 128>>>(rst, w_fc1, w_lin1, b1, ft, sk,
                                      al1, ar1, gam0, be0, 0);
    gat_node_kernel<128, 32, 0><<<NODB, 256>>>(nullptr, nullptr, 1);

    // ---- layer 2 (BN stats from buffer 1) + fused final ----
    gemm_tc<160, true><<<g160, 128>>>(rst, w_fc2, w_lin2, b2, ft, sk,
                                      nullptr, nullptr, gam1, be1, 1);
    elr40_kernel<<<NHB, 256>>>(al2, ar2);
    gat_node_kernel<160, 40, 1><<<NODB, 256>>>(blast, (float*)d_out, 0);
}

// round 12
// speedup vs baseline: 2.5637x; 1.1761x over previous
#include <cuda_runtime.h>
#include <cuda_bf16.h>
#include <math.h>
#include <float.h>

#define NN 50000
#define EE 800000

// ---------------- persistent scratch (device globals; no allocation) ----------------
__device__ __nv_bfloat16 g_ftb[NN * 160];   // transformed features [N, H*F], bf16
__device__ float g_rst[NN * 160];   // layer output (post message-passing)
__device__ float g_sk [NN * 160];   // skip + bias buffer
__device__ float g_el [NN * 4];
__device__ float g_er [NN * 4];
__device__ float g_ex [EE * 4];     // staging for rare high-degree nodes
__device__ int   g_rowptr[NN + 1];
__device__ int   g_tmp   [NN];
__device__ int   g_csr_src[EE];
__device__ float g_bnsum[2][128], g_bnsq[2][128];   // ping-pong BN stats

__device__ __forceinline__ float lrelu(float x) { return x > 0.f ? x : 0.2f * x; }

__device__ __forceinline__ float tf32r(float x) {
    unsigned u;
    asm("cvt.rna.tf32.f32 %0, %1;" : "=r"(u) : "f"(x));
    return __uint_as_float(u);
}

__device__ __forceinline__ void mma_tf32(float* c, const unsigned* a, const unsigned* b) {
    asm volatile(
        "mma.sync.aligned.m16n8k8.row.col.f32.tf32.tf32.f32 "
        "{%0,%1,%2,%3}, {%4,%5,%6,%7}, {%8,%9}, {%0,%1,%2,%3};\n"
        : "+f"(c[0]), "+f"(c[1]), "+f"(c[2]), "+f"(c[3])
        : "r"(a[0]), "r"(a[1]), "r"(a[2]), "r"(a[3]), "r"(b[0]), "r"(b[1]));
}

// load 4 consecutive bf16 (8 bytes) and widen to float4
__device__ __forceinline__ float4 ld_bf16x4(const __nv_bfloat16* p) {
    __nv_bfloat162 pr[2];
    *(uint2*)pr = *(const uint2*)p;
    float2 a = __bfloat1622float2(pr[0]);
    float2 b = __bfloat1622float2(pr[1]);
    return make_float4(a.x, a.y, b.x, b.y);
}

// ================= CSR build =================
__global__ void zero_all_kernel()
{
    int i = blockIdx.x * blockDim.x + threadIdx.x;
    if (i < NN)  g_tmp[i] = 0;
    if (i < 128) {
        g_bnsum[0][i] = 0.f; g_bnsq[0][i] = 0.f;
        g_bnsum[1][i] = 0.f; g_bnsq[1][i] = 0.f;
    }
}

__global__ void hist_kernel(const int* __restrict__ dst)
{
    int e = blockIdx.x * blockDim.x + threadIdx.x;
    if (e < EE) atomicAdd(&g_tmp[dst[e]], 1);
}

// one-block scan of all NN counts in dynamic smem -> g_rowptr & g_tmp
extern __shared__ int s_scan[];
__global__ __launch_bounds__(1024) void scan_all_kernel()
{
    __shared__ int wsum[32];
    const int t = threadIdx.x, lane = t & 31, wid = t >> 5;
    for (int i = t; i < NN; i += 1024) s_scan[i] = g_tmp[i];
    __syncthreads();

    const int C = (NN + 1023) / 1024;      // 49
    const int base = t * C;
    int sum = 0;
#pragma unroll 7
    for (int i = 0; i < C; i++) {
        int idx = base + i;
        if (idx < NN) sum += s_scan[idx];
    }
    int x = sum;
#pragma unroll
    for (int o = 1; o < 32; o <<= 1) {
        int y = __shfl_up_sync(0xffffffffu, x, o);
        if (lane >= o) x += y;
    }
    if (lane == 31) wsum[wid] = x;
    __syncthreads();
    if (wid == 0) {
        int w = wsum[lane];
#pragma unroll
        for (int o = 1; o < 32; o <<= 1) {
            int y = __shfl_up_sync(0xffffffffu, w, o);
            if (lane >= o) w += y;
        }
        wsum[lane] = w;
    }
    __syncthreads();
    int run = (x - sum) + (wid ? wsum[wid - 1] : 0);
#pragma unroll 7
    for (int i = 0; i < C; i++) {
        int idx = base + i;
        if (idx < NN) { int v = s_scan[idx]; s_scan[idx] = run; run += v; }
    }
    __syncthreads();
    for (int i = t; i < NN; i += 1024) {
        int v = s_scan[i];
        g_rowptr[i] = v;
        g_tmp[i]    = v;
    }
    if (t == 0) g_rowptr[NN] = EE;
}

__global__ void scatter_kernel(const int* __restrict__ src, const int* __restrict__ dst)
{
    int e = blockIdx.x * blockDim.x + threadIdx.x;
    if (e >= EE) return;
    int pos = atomicAdd(&g_tmp[dst[e]], 1);
    g_csr_src[pos] = src[e];
}

// ---------------- merged tf32 GEMM: warps 0-3 -> fc, warps 4-7 -> lin, shared A ----
// fc output -> bf16 g_ftb (+ optional fused el/er for OD=128); lin -> fp32 sk (+bias)
// BN: x <- relu(a*x+b) on A-tile load; scale/shift computed in-block from raw stats.
template<int OD, bool BN>
__global__ __launch_bounds__(256)
void gemm_tc(const float* __restrict__ X,
             const float* __restrict__ Wfc, const float* __restrict__ Wlin,
             const float* __restrict__ bias, __nv_bfloat16* __restrict__ ft_out,
             float* __restrict__ sk_out,
             const float* __restrict__ al, const float* __restrict__ ar,
             const float* __restrict__ gam, const float* __restrict__ be, int sel)
{
    __shared__ float As[128 * 37];        // [m][k]
    __shared__ float Bs[2 * 32 * 37];     // [mat][n][k]
    __shared__ float s_a[128], s_b[128];
    const int tid  = threadIdx.x;
    const int warp = tid >> 5, lane = tid & 31;
    const int g    = lane >> 2, t = lane & 3;
    const bool isFC = warp < 4;
    const int wr   = warp & 3;            // row-group within matrix
    const int row0 = blockIdx.x * 128;
    const int cb   = blockIdx.y;
    const int col0 = cb * 32;

    if (BN) {
        if (tid < 128) {
            float sum = g_bnsum[sel][tid], sq = g_bnsq[sel][tid];
            const float invN = 1.f / (float)NN;
            float mean = sum * invN;
            float var  = sq * invN - mean * mean;
            float a = __ldg(gam + tid) * rsqrtf(var + 1e-5f);
            s_a[tid] = a;
            s_b[tid] = __ldg(be + tid) - mean * a;
        }
        __syncthreads();
    }

    float c[2][4][4];
#pragma unroll
    for (int i = 0; i < 2; i++)
#pragma unroll
        for (int j = 0; j < 4; j++)
#pragma unroll
            for (int q = 0; q < 4; q++) c[i][j][q] = 0.f;

#pragma unroll
    for (int kb = 0; kb < 128; kb += 32) {
        // A tile: 128 rows x 32 k (1024 float4 slots / 256 threads = 4 iters)
#pragma unroll
        for (int j = 0; j < 4; j++) {
            int i4 = tid + j * 256;
            int r  = i4 >> 3;
            int k4 = (i4 & 7) << 2;
            float4 v = make_float4(0.f, 0.f, 0.f, 0.f);
            if (row0 + r < NN)
                v = *(const float4*)(X + (size_t)(row0 + r) * 128 + kb + k4);
            if (BN) {
                v.x = fmaxf(s_a[kb + k4 + 0] * v.x + s_b[kb + k4 + 0], 0.f);
                v.y = fmaxf(s_a[kb + k4 + 1] * v.y + s_b[kb + k4 + 1], 0.f);
                v.z = fmaxf(s_a[kb + k4 + 2] * v.z + s_b[kb + k4 + 2], 0.f);
                v.w = fmaxf(s_a[kb + k4 + 3] * v.w + s_b[kb + k4 + 3], 0.f);
            }
            float* ap = &As[r * 37 + k4];
            ap[0] = tf32r(v.x); ap[1] = tf32r(v.y); ap[2] = tf32r(v.z); ap[3] = tf32r(v.w);
        }
        // B tiles: both matrices, 512 float4 slots / 256 threads = 2 iters
#pragma unroll
        for (int j = 0; j < 2; j++) {
            int i4 = tid + j * 256;
            int m  = i4 >> 8;
            int rr = i4 & 255;
            int k  = rr >> 3;
            int n4 = (rr & 7) << 2;
            const float* Wm = m ? Wlin : Wfc;
            float4 v = *(const float4*)(Wm + (size_t)(kb + k) * OD + col0 + n4);
            float* bp = Bs + m * (32 * 37);
            bp[(n4 + 0) * 37 + k] = tf32r(v.x);
            bp[(n4 + 1) * 37 + k] = tf32r(v.y);
            bp[(n4 + 2) * 37 + k] = tf32r(v.z);
            bp[(n4 + 3) * 37 + k] = tf32r(v.w);
        }
        __syncthreads();
        const float* Bsel = Bs + (isFC ? 0 : 1) * (32 * 37);
#pragma unroll
        for (int ks = 0; ks < 4; ks++) {
            const int k0 = ks * 8;
            unsigned a[2][4], b[4][2];
            const int mbase = wr * 32;
#pragma unroll
            for (int i = 0; i < 2; i++) {
                const float* ap = As + (mbase + i * 16 + g) * 37 + k0 + t;
                a[i][0] = __float_as_uint(ap[0]);
                a[i][1] = __float_as_uint(ap[8 * 37]);
                a[i][2] = __float_as_uint(ap[4]);
                a[i][3] = __float_as_uint(ap[8 * 37 + 4]);
            }
#pragma unroll
            for (int j = 0; j < 4; j++) {
                const float* bp = Bsel + (j * 8 + g) * 37 + k0 + t;
                b[j][0] = __float_as_uint(bp[0]);
                b[j][1] = __float_as_uint(bp[4]);
            }
#pragma unroll
            for (int i = 0; i < 2; i++)
#pragma unroll
                for (int j = 0; j < 4; j++)
                    mma_tf32(c[i][j], a[i], b[j]);
        }
        __syncthreads();
    }

#pragma unroll
    for (int i = 0; i < 2; i++) {
        int r = row0 + wr * 32 + i * 16 + g;
#pragma unroll
        for (int j = 0; j < 4; j++) {
            int cc = col0 + j * 8 + 2 * t;
            if (isFC) {
                if (r < NN) {
                    __nv_bfloat162 o = __float22bfloat162_rn(
                        make_float2(c[i][j][0], c[i][j][1]));
                    *(__nv_bfloat162*)(ft_out + (size_t)r * OD + cc) = o;
                }
                if (r + 8 < NN) {
                    __nv_bfloat162 o = __float22bfloat162_rn(
                        make_float2(c[i][j][2], c[i][j][3]));
                    *(__nv_bfloat162*)(ft_out + (size_t)(r + 8) * OD + cc) = o;
                }
            } else {
                float bx = __ldg(bias + cc), by = __ldg(bias + cc + 1);
                if (r < NN) {
                    float2 o = make_float2(c[i][j][0] + bx, c[i][j][1] + by);
                    *(float2*)(sk_out + (size_t)r * OD + cc) = o;
                }
                if (r + 8 < NN) {
                    float2 o = make_float2(c[i][j][2] + bx, c[i][j][3] + by);
                    *(float2*)(sk_out + (size_t)(r + 8) * OD + cc) = o;
                }
            }
        }
    }

    if (OD == 128 && isFC && al != nullptr) {   // fused el/er: col block cb == head
        const int h = cb;
#pragma unroll
        for (int i = 0; i < 2; i++) {
            float el0 = 0.f, el8 = 0.f, er0 = 0.f, er8 = 0.f;
#pragma unroll
            for (int j = 0; j < 4; j++) {
                int lc = j * 8 + 2 * t;
                float a0 = __ldg(al + h * 32 + lc), a1 = __ldg(al + h * 32 + lc + 1);
                float r0 = __ldg(ar + h * 32 + lc), r1 = __ldg(ar + h * 32 + lc + 1);
                el0 += c[i][j][0] * a0 + c[i][j][1] * a1;
                el8 += c[i][j][2] * a0 + c[i][j][3] * a1;
                er0 += c[i][j][0] * r0 + c[i][j][1] * r1;
                er8 += c[i][j][2] * r0 + c[i][j][3] * r1;
            }
#pragma unroll
            for (int o = 1; o <= 2; o <<= 1) {
                el0 += __shfl_xor_sync(0xffffffffu, el0, o);
                el8 += __shfl_xor_sync(0xffffffffu, el8, o);
                er0 += __shfl_xor_sync(0xffffffffu, er0, o);
                er8 += __shfl_xor_sync(0xffffffffu, er8, o);
            }
            if (t == 0) {
                int r = row0 + wr * 32 + i * 16 + g;
                if (r < NN)     { g_el[r * 4 + h] = el0;       g_er[r * 4 + h] = er0; }
                if (r + 8 < NN) { g_el[(r + 8) * 4 + h] = el8; g_er[(r + 8) * 4 + h] = er8; }
            }
        }
    }
}

// ---------------- el/er for layer 2 (F=40, heads not block-aligned) ----------------
__global__ void elr40_kernel(const float* __restrict__ al, const float* __restrict__ ar)
{
    int i = blockIdx.x * blockDim.x + threadIdx.x;
    if (i >= NN * 4) return;
    int h = i & 3;
    const __nv_bfloat16* f = g_ftb + (size_t)(i >> 2) * 160 + h * 40;
    float a = 0.f, b = 0.f;
#pragma unroll
    for (int j = 0; j < 10; j++) {
        float4 v = ld_bf16x4(f + j * 4);
        float a0 = __ldg(al + h * 40 + j * 4 + 0), a1 = __ldg(al + h * 40 + j * 4 + 1);
        float a2 = __ldg(al + h * 40 + j * 4 + 2), a3 = __ldg(al + h * 40 + j * 4 + 3);
        float b0 = __ldg(ar + h * 40 + j * 4 + 0), b1 = __ldg(ar + h * 40 + j * 4 + 1);
        float b2 = __ldg(ar + h * 40 + j * 4 + 2), b3 = __ldg(ar + h * 40 + j * 4 + 3);
        a += v.x * a0 + v.y * a1 + v.z * a2 + v.w * a3;
        b += v.x * b0 + v.y * b1 + v.z * b2 + v.w * b3;
    }
    g_el[i] = a;
    g_er[i] = b;
}

// ================= fused per-dst softmax + aggregation (warp per node) =========
// MODE 0: rst = sk + msg, accumulate BN stats into buffer [sel].
// MODE 1: head-mean + log_softmax -> out.
template<int OD, int F, int MODE>
__global__ __launch_bounds__(256)
void gat_node_kernel(const float* __restrict__ bias_last, float* __restrict__ out, int sel)
{
    constexpr int NR = (OD / 4 + 31) / 32;
    __shared__ float s_sum[128], s_sq[128];
    __shared__ float s_row[8][160];
    __shared__ int   s_sn [8][32];
    __shared__ float s_att[8][32][4];

    const int tid = threadIdx.x;
    if (MODE == 0) {
        if (tid < 128) { s_sum[tid] = 0.f; s_sq[tid] = 0.f; }
        __syncthreads();
    }
    const int wn   = (blockIdx.x * 256 + tid) >> 5;
    const int lane = tid & 31;
    const int warp = tid >> 5;
    const bool active = wn < NN;

    float4 acc[NR];
    int headr[NR];
#pragma unroll
    for (int rp = 0; rp < NR; rp++) {
        acc[rp] = make_float4(0.f, 0.f, 0.f, 0.f);
        headr[rp] = ((lane + rp * 32) * 4) / F;
    }

    if (active) {
        const int beg = g_rowptr[wn], end = g_rowptr[wn + 1];
        const int deg = end - beg;
        const float4 er = *(const float4*)(g_er + (size_t)wn * 4);

        if (deg <= 32) {
            // ---- one gather pass, lane-local edge ----
            int sn = -1;
            float4 ev = make_float4(-FLT_MAX, -FLT_MAX, -FLT_MAX, -FLT_MAX);
            if (lane < deg) {
                sn = g_csr_src[beg + lane];
                float4 l = *(const float4*)(g_el + (size_t)sn * 4);
                ev.x = lrelu(l.x + er.x);
                ev.y = lrelu(l.y + er.y);
                ev.z = lrelu(l.z + er.z);
                ev.w = lrelu(l.w + er.w);
            }
            float4 m = ev;
#pragma unroll
            for (int o = 16; o; o >>= 1) {
                m.x = fmaxf(m.x, __shfl_xor_sync(0xffffffffu, m.x, o));
                m.y = fmaxf(m.y, __shfl_xor_sync(0xffffffffu, m.y, o));
                m.z = fmaxf(m.z, __shfl_xor_sync(0xffffffffu, m.z, o));
                m.w = fmaxf(m.w, __shfl_xor_sync(0xffffffffu, m.w, o));
            }
            float4 ex = make_float4(0.f, 0.f, 0.f, 0.f);
            if (lane < deg) {
                ex.x = __expf(ev.x - m.x);
                ex.y = __expf(ev.y - m.y);
                ex.z = __expf(ev.z - m.z);
                ex.w = __expf(ev.w - m.w);
            }
            float4 s = ex;
#pragma unroll
            for (int o = 16; o; o >>= 1) {
                s.x += __shfl_xor_sync(0xffffffffu, s.x, o);
                s.y += __shfl_xor_sync(0xffffffffu, s.y, o);
                s.z += __shfl_xor_sync(0xffffffffu, s.z, o);
                s.w += __shfl_xor_sync(0xffffffffu, s.w, o);
            }
            s_sn[warp][lane] = sn;
            s_att[warp][lane][0] = ex.x / s.x;
            s_att[warp][lane][1] = ex.y / s.y;
            s_att[warp][lane][2] = ex.z / s.z;
            s_att[warp][lane][3] = ex.w / s.w;
            __syncwarp();

            for (int i = 0; i < deg; i++) {
                int si = s_sn[warp][i];
                const __nv_bfloat16* fp = g_ftb + (size_t)si * OD;
#pragma unroll
                for (int rp = 0; rp < NR; rp++) {
                    int j4 = lane + rp * 32;
                    if (j4 < OD / 4) {
                        float a = s_att[warp][i][headr[rp]];
                        float4 f = ld_bf16x4(fp + j4 * 4);
                        acc[rp].x += a * f.x;
                        acc[rp].y += a * f.y;
                        acc[rp].z += a * f.z;
                        acc[rp].w += a * f.w;
                    }
                }
            }
        } else {
            // ---- rare high-degree fallback: 3-phase with staging ----
            float4 m = make_float4(-FLT_MAX, -FLT_MAX, -FLT_MAX, -FLT_MAX);
            for (int i = beg + lane; i < end; i += 32) {
                int sn = g_csr_src[i];
                float4 l = *(const float4*)(g_el + (size_t)sn * 4);
                m.x = fmaxf(m.x, lrelu(l.x + er.x));
                m.y = fmaxf(m.y, lrelu(l.y + er.y));
                m.z = fmaxf(m.z, lrelu(l.z + er.z));
                m.w = fmaxf(m.w, lrelu(l.w + er.w));
            }
#pragma unroll
            for (int o = 16; o; o >>= 1) {
                m.x = fmaxf(m.x, __shfl_xor_sync(0xffffffffu, m.x, o));
                m.y = fmaxf(m.y, __shfl_xor_sync(0xffffffffu, m.y, o));
                m.z = fmaxf(m.z, __shfl_xor_sync(0xffffffffu, m.z, o));
                m.w = fmaxf(m.w, __shfl_xor_sync(0xffffffffu, m.w, o));
            }
            float4 s = make_float4(0.f, 0.f, 0.f, 0.f);
            for (int i = beg + lane; i < end; i += 32) {
                int sn = g_csr_src[i];
                float4 l = *(const float4*)(g_el + (size_t)sn * 4);
                float4 ex;
                ex.x = __expf(lrelu(l.x + er.x) - m.x);
                ex.y = __expf(lrelu(l.y + er.y) - m.y);
                ex.z = __expf(lrelu(l.z + er.z) - m.z);
                ex.w = __expf(lrelu(l.w + er.w) - m.w);
                *(float4*)(g_ex + (size_t)i * 4) = ex;
                s.x += ex.x; s.y += ex.y; s.z += ex.z; s.w += ex.w;
            }
#pragma unroll
            for (int o = 16; o; o >>= 1) {
                s.x += __shfl_xor_sync(0xffffffffu, s.x, o);
                s.y += __shfl_xor_sync(0xffffffffu, s.y, o);
                s.z += __shfl_xor_sync(0xffffffffu, s.z, o);
                s.w += __shfl_xor_sync(0xffffffffu, s.w, o);
            }
            float4 inv = make_float4(1.f / s.x, 1.f / s.y, 1.f / s.z, 1.f / s.w);
            float invh[NR];
#pragma unroll
            for (int rp = 0; rp < NR; rp++) {
                int hh = headr[rp];
                invh[rp] = (hh == 0) ? inv.x : (hh == 1) ? inv.y : (hh == 2) ? inv.z : inv.w;
            }
            for (int i = beg; i < end; i++) {
                int sn = g_csr_src[i];
                float4 exv = *(const float4*)(g_ex + (size_t)i * 4);
                const __nv_bfloat16* fp = g_ftb + (size_t)sn * OD;
#pragma unroll
                for (int rp = 0; rp < NR; rp++) {
                    int j4 = lane + rp * 32;
                    if (j4 < OD / 4) {
                        int hh = headr[rp];
                        float a = ((hh == 0) ? exv.x : (hh == 1) ? exv.y :
                                   (hh == 2) ? exv.z : exv.w) * invh[rp];
                        float4 f = ld_bf16x4(fp + j4 * 4);
                        acc[rp].x += a * f.x;
                        acc[rp].y += a * f.y;
                        acc[rp].z += a * f.z;
                        acc[rp].w += a * f.w;
                    }
                }
            }
        }
    }

    if (MODE == 0) {
        if (active) {
            const float* skp = g_sk  + (size_t)wn * OD;
            float*       rp_ = g_rst + (size_t)wn * OD;
#pragma unroll
            for (int rp = 0; rp < NR; rp++) {
                int j4 = lane + rp * 32;
                if (j4 < OD / 4) {
                    float4 sk = *(const float4*)(skp + j4 * 4);
                    float4 r;
                    r.x = sk.x + acc[rp].x; r.y = sk.y + acc[rp].y;
                    r.z = sk.z + acc[rp].z; r.w = sk.w + acc[rp].w;
                    *(float4*)(rp_ + j4 * 4) = r;
                    int c0 = j4 * 4;
                    atomicAdd(&s_sum[c0 + 0], r.x); atomicAdd(&s_sq[c0 + 0], r.x * r.x);
                    atomicAdd(&s_sum[c0 + 1], r.y); atomicAdd(&s_sq[c0 + 1], r.y * r.y);
                    atomicAdd(&s_sum[c0 + 2], r.z); atomicAdd(&s_sq[c0 + 2], r.z * r.z);
                    atomicAdd(&s_sum[c0 + 3], r.w); atomicAdd(&s_sq[c0 + 3], r.w * r.w);
                }
            }
        }
        __syncthreads();
        if (tid < 128) {
            atomicAdd(&g_bnsum[sel][tid], s_sum[tid]);
            atomicAdd(&g_bnsq[sel][tid],  s_sq[tid]);
        }
    } else {
        if (active) {
            const float* skp = g_sk + (size_t)wn * OD;
#pragma unroll
            for (int rp = 0; rp < NR; rp++) {
                int j4 = lane + rp * 32;
                if (j4 < OD / 4) {
                    float4 sk = *(const float4*)(skp + j4 * 4);
                    float* d = &s_row[warp][j4 * 4];
                    d[0] = sk.x + acc[rp].x;
                    d[1] = sk.y + acc[rp].y;
                    d[2] = sk.z + acc[rp].z;
                    d[3] = sk.w + acc[rp].w;
                }
            }
            __syncwarp();
            const float* r = s_row[warp];
            float v0 = 0.25f * (r[lane] + r[40 + lane] + r[80 + lane] + r[120 + lane])
                     + __ldg(bias_last + lane);
            float v1 = -FLT_MAX;
            if (lane < 8) {
                int c1 = lane + 32;
                v1 = 0.25f * (r[c1] + r[40 + c1] + r[80 + c1] + r[120 + c1])
                   + __ldg(bias_last + c1);
            }
            float mx = fmaxf(v0, v1);
#pragma unroll
            for (int o = 16; o; o >>= 1) mx = fmaxf(mx, __shfl_xor_sync(0xffffffffu, mx, o));
            float se = __expf(v0 - mx) + (lane < 8 ? __expf(v1 - mx) : 0.f);
#pragma unroll
            for (int o = 16; o; o >>= 1) se += __shfl_xor_sync(0xffffffffu, se, o);
            float lse = logf(se);
            out[(size_t)wn * 40 + lane] = v0 - mx - lse;
            if (lane < 8) out[(size_t)wn * 40 + lane + 32] = v1 - mx - lse;
        }
    }
}

// ---------------- launch ----------------
extern "C" void kernel_launch(void* const* d_in, const int* in_sizes, int n_in,
                              void* d_out, int out_size)
{
    (void)in_sizes; (void)n_in; (void)out_size;
    const float* feat   = (const float*)d_in[0];
    const int*   src    = (const int*)  d_in[1];
    const int*   dst    = (const int*)  d_in[2];
    const float* w_fc0  = (const float*)d_in[3];
    const float* al0    = (const float*)d_in[4];
    const float* ar0    = (const float*)d_in[5];
    const float* b0     = (const float*)d_in[6];
    const float* w_lin0 = (const float*)d_in[7];
    const float* gam0   = (const float*)d_in[8];
    const float* be0    = (const float*)d_in[9];
    const float* w_fc1  = (const float*)d_in[10];
    const float* al1    = (const float*)d_in[11];
    const float* ar1    = (const float*)d_in[12];
    const float* b1     = (const float*)d_in[13];
    const float* w_lin1 = (const float*)d_in[14];
    const float* gam1   = (const float*)d_in[15];
    const float* be1    = (const float*)d_in[16];
    const float* w_fc2  = (const float*)d_in[17];
    const float* al2    = (const float*)d_in[18];
    const float* ar2    = (const float*)d_in[19];
    const float* b2     = (const float*)d_in[20];
    const float* w_lin2 = (const float*)d_in[21];
    const float* blast  = (const float*)d_in[22];

    __nv_bfloat16* ftb;
    float *rst, *sk;
    cudaGetSymbolAddress((void**)&ftb, g_ftb);
    cudaGetSymbolAddress((void**)&rst, g_rst);
    cudaGetSymbolAddress((void**)&sk,  g_sk);

    static cudaStream_t s2 = nullptr;
    static cudaEvent_t evF = nullptr, evJ = nullptr;
    if (!s2) {
        cudaFuncSetAttribute(scan_all_kernel,
                             cudaFuncAttributeMaxDynamicSharedMemorySize, NN * 4);
        cudaStreamCreateWithFlags(&s2, cudaStreamNonBlocking);
        cudaEventCreateWithFlags(&evF, cudaEventDisableTiming);
        cudaEventCreateWithFlags(&evJ, cudaEventDisableTiming);
    }

    const dim3 g128((NN + 127) / 128, 4);    // 4 col-blocks, fc+lin per block
    const dim3 g160((NN + 127) / 128, 5);
    const int EB   = (EE + 255) / 256;
    const int NB   = (NN + 255) / 256;
    const int NODB = (NN * 32 + 255) / 256;  // warp per node
    const int NHB  = (NN * 4 + 255) / 256;

    // ---- fork: CSR build on s2, overlapped with layer-0 GEMM ----
    cudaEventRecord(evF, 0);
    cudaStreamWaitEvent(s2, evF, 0);
    zero_all_kernel<<<NB, 256, 0, s2>>>();
    hist_kernel<<<EB, 256, 0, s2>>>(dst);
    scan_all_kernel<<<1, 1024, NN * 4, s2>>>();
    scatter_kernel<<<EB, 256, 0, s2>>>(src, dst);
    cudaEventRecord(evJ, s2);

    // ---- layer 0 (runs concurrently with CSR build) ----
    gemm_tc<128, false><<<g128, 256>>>(feat, w_fc0, w_lin0, b0, ftb, sk,
                                       al0, ar0, nullptr, nullptr, 0);
    cudaStreamWaitEvent(0, evJ, 0);          // join before message passing
    gat_node_kernel<128, 32, 0><<<NODB, 256>>>(nullptr, nullptr, 0);

    // ---- layer 1 (BN+ReLU fused into A-tile load, stats from buffer 0) ----
    gemm_tc<128, true><<<g128, 256>>>(rst, w_fc1, w_lin1, b1, ftb, sk,
                                      al1, ar1, gam0, be0, 0);
    gat_node_kernel<128, 32, 0><<<NODB, 256>>>(nullptr, nullptr, 1);

    // ---- layer 2 (BN stats from buffer 1) + fused final ----
    gemm_tc<160, true><<<g160, 256>>>(rst, w_fc2, w_lin2, b2, ftb, sk,
                                      nullptr, nullptr, gam1, be1, 1);
    elr40_kernel<<<NHB, 256>>>(al2, ar2);
    gat_node_kernel<160, 40, 1><<<NODB, 256>>>(blast, (float*)d_out, 0);
}